// round 5
// baseline (speedup 1.0000x reference)
#include <cuda_runtime.h>
#include <math.h>

// ---------------- problem constants ----------------
constexpr int CB  = 4;      // batch
constexpr int CC  = 512;    // channels
constexpr int CHH = 32;     // H
constexpr int CWW = 32;     // W
constexpr int CHW = 1024;   // H*W
constexpr int CNH = 8;      // heads
constexpr int NPR = 8;      // prompt tokens
constexpr int CN  = 1032;   // total tokens
constexpr int HID = 1024;   // mlp hidden
constexpr float EPS = 1e-5f;

// ---------------- scratch (static device memory; no allocations) ----------------
__device__ __align__(16) float g_dw1 [CB*CC*CHW];
__device__ __align__(16) float g_dsf [CB*CC*CHW];
__device__ __align__(16) float g_pp1t[CB*CHW*CC];
__device__ __align__(16) float g_pp2t[CB*CHW*CC];
__device__ __align__(16) float g_ds  [CB*CHW];
__device__ __align__(16) float g_prompt[CB*NPR*CC];
__device__ __align__(16) float g_jd  [CB*CN];
__device__ __align__(16) float g_jt  [CB*CN*CC];
__device__ __align__(16) float g_x   [CB*CN*CC];
__device__ __align__(16) float g_q   [CB*CN*CC];
__device__ __align__(16) float g_k   [CB*CN*CC];
__device__ __align__(16) float g_v   [CB*CN*CC];
__device__ __align__(16) float g_ao  [CB*CN*CC];
__device__ __align__(16) float g_h   [CB*CN*HID];
__device__ __align__(16) float g_enh [CB*CC*CHW];
__device__ __align__(16) float g_o1c [CB*CC*CHW];
__device__ __align__(16) float g_o1t [CB*CHW*CC];
__device__ __align__(16) float g_o2t [CB*CHW*CC];

__device__ __forceinline__ float gelu_f(float x){
    return 0.5f * x * (1.0f + erff(x * 0.70710678118654752f));
}

__device__ __forceinline__ unsigned f2tf(float f){
    unsigned u;
    asm("cvt.rna.tf32.f32 %0, %1;" : "=r"(u) : "f"(f));
    return u;
}

__device__ __forceinline__ void mma_tf32(float& d0, float& d1, float& d2, float& d3,
                                         unsigned a0, unsigned a1, unsigned a2, unsigned a3,
                                         unsigned b0, unsigned b1)
{
    asm volatile("mma.sync.aligned.m16n8k8.row.col.f32.tf32.tf32.f32 "
                 "{%0,%1,%2,%3}, {%4,%5,%6,%7}, {%8,%9}, {%0,%1,%2,%3};"
                 : "+f"(d0), "+f"(d1), "+f"(d2), "+f"(d3)
                 : "r"(a0), "r"(a1), "r"(a2), "r"(a3), "r"(b0), "r"(b1));
}

// ---------------- depthwise 3x3 conv + BN + GELU (optionally two branches) ----------------
__global__ void k_dwconv_dual(const float* __restrict__ in,
                              const float* __restrict__ w1, const float* __restrict__ bn1,
                              float* __restrict__ out1,
                              const float* __restrict__ w2, const float* __restrict__ bn2,
                              float* __restrict__ out2)
{
    int idx = blockIdx.x * 256 + threadIdx.x;
    if (idx >= CB*CC*CHW) return;
    int p = idx & (CHW-1);
    int c = (idx >> 10) & (CC-1);
    int y = p >> 5, x = p & 31;
    const float* base = in + (size_t)(idx - p);
    float v[9];
#pragma unroll
    for (int ky = 0; ky < 3; ky++)
#pragma unroll
        for (int kx = 0; kx < 3; kx++){
            int yy = y + ky - 1, xx = x + kx - 1;
            v[ky*3+kx] = (yy >= 0 && yy < CHH && xx >= 0 && xx < CWW) ? base[yy*CWW + xx] : 0.f;
        }
    {
        float a = 0.f;
#pragma unroll
        for (int k = 0; k < 9; k++) a += w1[c*9+k] * v[k];
        float s = bn1[c] * rsqrtf(bn1[3*CC+c] + EPS);
        a = a * s + bn1[CC+c] - bn1[2*CC+c] * s;
        out1[idx] = gelu_f(a);
    }
    if (out2){
        float a = 0.f;
#pragma unroll
        for (int k = 0; k < 9; k++) a += w2[c*9+k] * v[k];
        float s = bn2[c] * rsqrtf(bn2[3*CC+c] + EPS);
        a = a * s + bn2[CC+c] - bn2[2*CC+c] * s;
        out2[idx] = gelu_f(a);
    }
}

// ---------------- transposes ----------------
__global__ void k_cp_to_tok(const float* __restrict__ in, float* __restrict__ out,
                            int tokTotal, int tokOff)
{
    __shared__ float tile[32][33];
    int b = blockIdx.z;
    int p0 = blockIdx.x * 32, c0 = blockIdx.y * 32;
    int tx = threadIdx.x, ty = threadIdx.y;
#pragma unroll
    for (int i = 0; i < 4; i++){
        int c = c0 + ty + i*8;
        tile[ty + i*8][tx] = in[((size_t)b*CC + c)*CHW + p0 + tx];
    }
    __syncthreads();
#pragma unroll
    for (int i = 0; i < 4; i++){
        int p = p0 + ty + i*8;
        out[((size_t)b*tokTotal + tokOff + p)*CC + c0 + tx] = tile[tx][ty + i*8];
    }
}

__global__ void k_tok_to_cp(const float* __restrict__ in, float* __restrict__ out,
                            int tokTotal, int tokOff)
{
    __shared__ float tile[32][33];
    int b = blockIdx.z;
    int p0 = blockIdx.x * 32, c0 = blockIdx.y * 32;
    int tx = threadIdx.x, ty = threadIdx.y;
#pragma unroll
    for (int i = 0; i < 4; i++){
        int p = p0 + ty + i*8;
        tile[ty + i*8][tx] = in[((size_t)b*tokTotal + tokOff + p)*CC + c0 + tx];
    }
    __syncthreads();
#pragma unroll
    for (int i = 0; i < 4; i++){
        int c = c0 + ty + i*8;
        out[((size_t)b*CC + c)*CHW + p0 + tx] = tile[tx][ty + i*8];
    }
}

// ---------------- tensor-core NT GEMM (tf32 mma), 128x128 tile, K-step 16 ----------------
// C[m,n] = sum_k A[m,k]*B[n,k].  EPI: 0 plain, 1 bn+gelu, 2 bias+gelu, 3 bias+res, 4 res
constexpr int GST = 20;   // padded SMEM stride (words), conflict-free for mma frag loads

template<int EPI>
__global__ void __launch_bounds__(256) k_gemm_tc(const float* __restrict__ A,
                                                 const float* __restrict__ Bw,
                                                 float* __restrict__ Cmat,
                                                 int M, int N, int K,
                                                 const float* __restrict__ ep,
                                                 const float* __restrict__ res)
{
    __shared__ unsigned As[2][128*GST];
    __shared__ unsigned Bs[2][128*GST];

    int tid  = threadIdx.x;
    int lane = tid & 31;
    int w    = tid >> 5;
    int wm   = w >> 1;         // 0..3 (M)
    int wn   = w & 1;          // 0..1 (N)
    int m0 = blockIdx.y * 128, n0 = blockIdx.x * 128;

    // load indices: 512 float4 per tile, 2 per thread
    int i0 = tid, i1 = tid + 256;
    int ar0 = i0 >> 2, ac0 = (i0 & 3) * 4;
    int ar1 = i1 >> 2, ac1 = (i1 & 3) * 4;

    float acc[2][8][4];
#pragma unroll
    for (int mf = 0; mf < 2; mf++)
#pragma unroll
        for (int nf = 0; nf < 8; nf++)
#pragma unroll
            for (int r = 0; r < 4; r++) acc[mf][nf][r] = 0.f;

    int NK = K >> 4;

    // prologue: tile 0
    {
        float4 a0 = (m0 + ar0 < M) ? *(const float4*)(A + (size_t)(m0 + ar0)*K + ac0) : make_float4(0,0,0,0);
        float4 a1 = (m0 + ar1 < M) ? *(const float4*)(A + (size_t)(m0 + ar1)*K + ac1) : make_float4(0,0,0,0);
        float4 b0 = *(const float4*)(Bw + (size_t)(n0 + ar0)*K + ac0);
        float4 b1 = *(const float4*)(Bw + (size_t)(n0 + ar1)*K + ac1);
        *(uint4*)&As[0][ar0*GST + ac0] = make_uint4(f2tf(a0.x), f2tf(a0.y), f2tf(a0.z), f2tf(a0.w));
        *(uint4*)&As[0][ar1*GST + ac1] = make_uint4(f2tf(a1.x), f2tf(a1.y), f2tf(a1.z), f2tf(a1.w));
        *(uint4*)&Bs[0][ar0*GST + ac0] = make_uint4(f2tf(b0.x), f2tf(b0.y), f2tf(b0.z), f2tf(b0.w));
        *(uint4*)&Bs[0][ar1*GST + ac1] = make_uint4(f2tf(b1.x), f2tf(b1.y), f2tf(b1.z), f2tf(b1.w));
    }
    __syncthreads();

    for (int kt = 0; kt < NK; kt++){
        float4 a0, a1, b0, b1;
        bool has_next = (kt + 1 < NK);
        if (has_next){
            int kb = (kt + 1) << 4;
            a0 = (m0 + ar0 < M) ? *(const float4*)(A + (size_t)(m0 + ar0)*K + kb + ac0) : make_float4(0,0,0,0);
            a1 = (m0 + ar1 < M) ? *(const float4*)(A + (size_t)(m0 + ar1)*K + kb + ac1) : make_float4(0,0,0,0);
            b0 = *(const float4*)(Bw + (size_t)(n0 + ar0)*K + kb + ac0);
            b1 = *(const float4*)(Bw + (size_t)(n0 + ar1)*K + kb + ac1);
        }
        const unsigned* Ac = As[kt & 1];
        const unsigned* Bc = Bs[kt & 1];
#pragma unroll
        for (int kf = 0; kf < 2; kf++){
            int kc = kf*8 + (lane & 3);
            unsigned afr[2][4];
#pragma unroll
            for (int mf = 0; mf < 2; mf++){
                int rbase = wm*32 + mf*16 + (lane >> 2);
                afr[mf][0] = Ac[(rbase    )*GST + kc    ];
                afr[mf][1] = Ac[(rbase + 8)*GST + kc    ];
                afr[mf][2] = Ac[(rbase    )*GST + kc + 4];
                afr[mf][3] = Ac[(rbase + 8)*GST + kc + 4];
            }
#pragma unroll
            for (int nf = 0; nf < 8; nf++){
                int nb = wn*64 + nf*8 + (lane >> 2);
                unsigned bb0 = Bc[nb*GST + kc];
                unsigned bb1 = Bc[nb*GST + kc + 4];
#pragma unroll
                for (int mf = 0; mf < 2; mf++)
                    mma_tf32(acc[mf][nf][0], acc[mf][nf][1], acc[mf][nf][2], acc[mf][nf][3],
                             afr[mf][0], afr[mf][1], afr[mf][2], afr[mf][3], bb0, bb1);
            }
        }
        if (has_next){
            unsigned bi = (kt + 1) & 1;
            *(uint4*)&As[bi][ar0*GST + ac0] = make_uint4(f2tf(a0.x), f2tf(a0.y), f2tf(a0.z), f2tf(a0.w));
            *(uint4*)&As[bi][ar1*GST + ac1] = make_uint4(f2tf(a1.x), f2tf(a1.y), f2tf(a1.z), f2tf(a1.w));
            *(uint4*)&Bs[bi][ar0*GST + ac0] = make_uint4(f2tf(b0.x), f2tf(b0.y), f2tf(b0.z), f2tf(b0.w));
            *(uint4*)&Bs[bi][ar1*GST + ac1] = make_uint4(f2tf(b1.x), f2tf(b1.y), f2tf(b1.z), f2tf(b1.w));
        }
        __syncthreads();
    }

    // epilogue
#pragma unroll
    for (int mf = 0; mf < 2; mf++){
#pragma unroll
        for (int ri = 0; ri < 2; ri++){
            int row = m0 + wm*32 + mf*16 + (lane >> 2) + ri*8;
            if (row >= M) continue;
            size_t base = (size_t)row * N;
#pragma unroll
            for (int nf = 0; nf < 8; nf++){
                int col = n0 + wn*64 + nf*8 + 2*(lane & 3);
                float v0 = acc[mf][nf][ri*2 + 0];
                float v1 = acc[mf][nf][ri*2 + 1];
                if (EPI == 1){
                    float s0 = ep[col]   * rsqrtf(ep[3*N+col]   + EPS);
                    float s1 = ep[col+1] * rsqrtf(ep[3*N+col+1] + EPS);
                    v0 = gelu_f(v0 * s0 + ep[N+col]   - ep[2*N+col]   * s0);
                    v1 = gelu_f(v1 * s1 + ep[N+col+1] - ep[2*N+col+1] * s1);
                } else if (EPI == 2){
                    v0 = gelu_f(v0 + ep[col]);
                    v1 = gelu_f(v1 + ep[col+1]);
                } else if (EPI == 3){
                    float2 rr = *(const float2*)(res + base + col);
                    v0 = rr.x + v0 + ep[col];
                    v1 = rr.y + v1 + ep[col+1];
                } else if (EPI == 4){
                    float2 rr = *(const float2*)(res + base + col);
                    v0 = rr.x + v0;
                    v1 = rr.y + v1;
                }
                *(float2*)(Cmat + base + col) = make_float2(v0, v1);
            }
        }
    }
}

// ---------------- geometry prior: 512->1 projection (parallel) ----------------
__global__ void k_gp_pw(const float* __restrict__ dsf, const float* __restrict__ w,
                        const float* __restrict__ bias, float* __restrict__ ds)
{
    // block: 256 threads = 32 pixels x 8 channel-chunks of 64
    __shared__ float red[8][33];
    int px = threadIdx.x & 31;
    int cz = threadIdx.x >> 5;
    int p0 = blockIdx.x * 32;
    int b  = p0 >> 10;
    int p  = (p0 & (CHW-1)) + px;
    float acc = 0.f;
#pragma unroll
    for (int i = 0; i < 64; i++){
        int c = cz*64 + i;
        acc += w[c] * dsf[((size_t)b*CC + c)*CHW + p];
    }
    red[cz][px] = acc;
    __syncthreads();
    if (cz == 0){
        float s = 0.f;
#pragma unroll
        for (int z = 0; z < 8; z++) s += red[z][px];
        ds[p0 + px] = s + bias[0];
    }
}

// ---------------- prompt: pool + embed + LN ----------------
__global__ void k_prompt(const float* __restrict__ pp2t, const float* __restrict__ pe,
                         const float* __restrict__ lnp, float* __restrict__ out)
{
    int b = blockIdx.x >> 3, pr = blockIdx.x & 7;
    int iy = pr >> 2, ix = pr & 3;
    int t = threadIdx.x;
    float a0 = 0.f, a1 = 0.f;
    for (int py = 0; py < 16; py++)
        for (int px = 0; px < 8; px++){
            int p = (iy*16 + py)*CWW + ix*8 + px;
            const float* base = pp2t + ((size_t)b*CHW + p)*CC;
            a0 += base[t];
            a1 += base[t + 256];
        }
    a0 = a0 * (1.f/128.f) + pe[pr*CC + t];
    a1 = a1 * (1.f/128.f) + pe[pr*CC + t + 256];
    __shared__ float rs[256], rq[256];
    rs[t] = a0 + a1; rq[t] = a0*a0 + a1*a1;
    __syncthreads();
    for (int s = 128; s > 0; s >>= 1){
        if (t < s){ rs[t] += rs[t+s]; rq[t] += rq[t+s]; }
        __syncthreads();
    }
    float mean = rs[0] * (1.f/512.f);
    float var  = rq[0] * (1.f/512.f) - mean*mean;
    float inv  = rsqrtf(var + EPS);
    size_t o = ((size_t)b*NPR + pr) * CC;
    out[o + t]       = (a0 - mean) * inv * lnp[t]       + lnp[CC + t];
    out[o + t + 256] = (a1 - mean) * inv * lnp[t + 256] + lnp[CC + t + 256];
}

// ---------------- joint depth scalar per token ----------------
__global__ void k_jd(const float* __restrict__ ds, float* __restrict__ jd)
{
    int t = blockIdx.x * 256 + threadIdx.x;
    if (t >= CB*CN) return;
    int b = t / CN, n = t % CN;
    if (n >= NPR){
        jd[t] = ds[b*CHW + (n - NPR)];
    } else {
        int iy = n >> 2, ix = n & 3;
        float acc = 0.f;
        for (int py = 0; py < 16; py++)
            for (int px = 0; px < 8; px++)
                acc += ds[b*CHW + (iy*16 + py)*CWW + ix*8 + px];
        jd[t] = acc * (1.f/128.f);
    }
}

// ---------------- copy prompt tokens into jt ----------------
__global__ void k_copy_prompt(const float* __restrict__ pr, float* __restrict__ jt)
{
    int idx = blockIdx.x * 256 + threadIdx.x;
    if (idx >= CB*NPR*CC) return;
    int b = idx / (NPR*CC), r = idx % (NPR*CC);
    jt[(size_t)b*CN*CC + r] = pr[(size_t)b*NPR*CC + r];
}

// ---------------- layernorm over C per token ----------------
__global__ void k_ln(const float* __restrict__ in, const float* __restrict__ p,
                     float* __restrict__ out)
{
    int tok = blockIdx.x;
    const float* row = in + (size_t)tok * CC;
    int t = threadIdx.x;
    float v0 = row[t], v1 = row[t + 256];
    __shared__ float rs[256], rq[256];
    rs[t] = v0 + v1; rq[t] = v0*v0 + v1*v1;
    __syncthreads();
    for (int s = 128; s > 0; s >>= 1){
        if (t < s){ rs[t] += rs[t+s]; rq[t] += rq[t+s]; }
        __syncthreads();
    }
    float mean = rs[0] * (1.f/512.f);
    float var  = rq[0] * (1.f/512.f) - mean*mean;
    float inv  = rsqrtf(var + EPS);
    size_t o = (size_t)tok * CC;
    out[o + t]       = (v0 - mean) * inv * p[t]       + p[CC + t];
    out[o + t + 256] = (v1 - mean) * inv * p[t + 256] + p[CC + t + 256];
}

// ---------------- attention: flash-style, tf32 mma, analytic bias ----------------
__device__ __forceinline__ void tok_coord(int n, float& cy, float& cx){
    if (n < NPR){ cy = (float)(n >> 2); cx = (float)(n & 3) * (1.f/3.f); }
    else { int m = n - NPR; cy = (float)(m >> 5) * (1.f/31.f); cx = (float)(m & 31) * (1.f/31.f); }
}

constexpr int QS_OFF = 0;                    // 128 x 68
constexpr int KS_OFF = QS_OFF + 128*68;      // 64 x 68
constexpr int VS_OFF = KS_OFF + 64*68;       // 64 x 72
constexpr int PS_OFF = VS_OFF + 64*72;       // 128 x 68
constexpr int KD_OFF = PS_OFF + 128*68;      // 64 floats
constexpr int ATTN_SMEM = (KD_OFF + 64) * 4; // bytes

__global__ void __launch_bounds__(256) k_attn(const float* __restrict__ qg,
                                              const float* __restrict__ kg,
                                              const float* __restrict__ vg,
                                              const float* __restrict__ jd,
                                              const float* __restrict__ gw,
                                              float* __restrict__ ao)
{
    extern __shared__ unsigned smu[];
    unsigned* Qs = smu + QS_OFF;
    unsigned* Ks = smu + KS_OFF;
    unsigned* Vs = smu + VS_OFF;
    unsigned* Ps = smu + PS_OFF;
    float*  kdep = (float*)(smu + KD_OFF);

    int b = blockIdx.z, h = blockIdx.y, q0 = blockIdx.x * 128;
    int tid = threadIdx.x, lane = tid & 31, w = tid >> 5;

    const float decay = logf(1.f - exp2f(-1.f - 0.5f * (float)h));
    const float w0 = gw[0] * decay, w1 = gw[1] * decay;

    // load Q tile (128 x 64), tf32, stride 68
    {
#pragma unroll
        for (int j = 0; j < 8; j++){
            int i = tid + 256*j;            // float4 index: 16 per row
            int r = i >> 4, c4 = (i & 15) * 4;
            int qn = q0 + r;
            float4 v = (qn < CN) ? *(const float4*)(qg + ((size_t)b*CN + qn)*CC + h*64 + c4)
                                 : make_float4(0,0,0,0);
            *(uint4*)&Qs[r*68 + c4] = make_uint4(f2tf(v.x), f2tf(v.y), f2tf(v.z), f2tf(v.w));
        }
    }

    // q-row metadata (2 rows per thread)
    float qy[2], qx[2], qd[2];
#pragma unroll
    for (int i = 0; i < 2; i++){
        int qn = q0 + w*16 + (lane >> 2) + i*8;
        if (qn < CN){ tok_coord(qn, qy[i], qx[i]); qd[i] = jd[b*CN + qn]; }
        else { qy[i] = qx[i] = qd[i] = 0.f; }
    }

    float O[8][4];
#pragma unroll
    for (int nf = 0; nf < 8; nf++)
#pragma unroll
        for (int r = 0; r < 4; r++) O[nf][r] = 0.f;
    float mi[2] = {-1e30f, -1e30f}, li[2] = {0.f, 0.f};

    for (int kt = 0; kt < 17; kt++){
        int k0 = kt * 64;
        __syncthreads();   // previous tile fully consumed
        // load K, V tiles (64 x 64)
#pragma unroll
        for (int j = 0; j < 4; j++){
            int i = tid + 256*j;
            int r = i >> 4, c4 = (i & 15) * 4;
            int n = k0 + r;
            bool val = (n < CN);
            float4 kv = val ? *(const float4*)(kg + ((size_t)b*CN + n)*CC + h*64 + c4) : make_float4(0,0,0,0);
            float4 vv = val ? *(const float4*)(vg + ((size_t)b*CN + n)*CC + h*64 + c4) : make_float4(0,0,0,0);
            *(uint4*)&Ks[r*68 + c4] = make_uint4(f2tf(kv.x), f2tf(kv.y), f2tf(kv.z), f2tf(kv.w));
            *(uint4*)&Vs[r*72 + c4] = make_uint4(f2tf(vv.x), f2tf(vv.y), f2tf(vv.z), f2tf(vv.w));
        }
        if (tid < 64) kdep[tid] = (k0 + tid < CN) ? jd[b*CN + k0 + tid] : 0.f;
        __syncthreads();

        // S = Q K^T (warp computes its 16 rows x 64 cols)
        float S[8][4];
#pragma unroll
        for (int nf = 0; nf < 8; nf++)
#pragma unroll
            for (int r = 0; r < 4; r++) S[nf][r] = 0.f;
#pragma unroll
        for (int kf = 0; kf < 8; kf++){
            int kc = kf*8 + (lane & 3);
            int rbase = w*16 + (lane >> 2);
            unsigned a0 = Qs[(rbase    )*68 + kc    ];
            unsigned a1 = Qs[(rbase + 8)*68 + kc    ];
            unsigned a2 = Qs[(rbase    )*68 + kc + 4];
            unsigned a3 = Qs[(rbase + 8)*68 + kc + 4];
#pragma unroll
            for (int nf = 0; nf < 8; nf++){
                int nb = nf*8 + (lane >> 2);
                unsigned b0 = Ks[nb*68 + kc];
                unsigned b1 = Ks[nb*68 + kc + 4];
                mma_tf32(S[nf][0], S[nf][1], S[nf][2], S[nf][3], a0, a1, a2, a3, b0, b1);
            }
        }

        // bias + scale, validity
        bool kval[8][2];
#pragma unroll
        for (int nf = 0; nf < 8; nf++){
#pragma unroll
            for (int j = 0; j < 2; j++){
                int kl = nf*8 + (lane & 3)*2 + j;
                int kn = k0 + kl;
                kval[nf][j] = (kn < CN);
                float ky, kx;
                tok_coord(kn, ky, kx);
                float kd = kdep[kl];
#pragma unroll
                for (int i = 0; i < 2; i++){
                    float pos = fabsf(qy[i]-ky) + fabsf(qx[i]-kx);
                    float vv = S[nf][i*2+j]*0.125f + w0*pos + w1*fabsf(qd[i]-kd);
                    S[nf][i*2+j] = kval[nf][j] ? vv : -1e30f;
                }
            }
        }

        // online softmax per row (quad reduction)
        float alpha[2];
#pragma unroll
        for (int i = 0; i < 2; i++){
            float tm = -1e30f;
#pragma unroll
            for (int nf = 0; nf < 8; nf++){
                tm = fmaxf(tm, S[nf][i*2]);
                tm = fmaxf(tm, S[nf][i*2+1]);
            }
            tm = fmaxf(tm, __shfl_xor_sync(0xffffffffu, tm, 1));
            tm = fmaxf(tm, __shfl_xor_sync(0xffffffffu, tm, 2));
            float mn = fmaxf(mi[i], tm);
            alpha[i] = __expf(mi[i] - mn);
            float ssum = 0.f;
#pragma unroll
            for (int nf = 0; nf < 8; nf++){
#pragma unroll
                for (int j = 0; j < 2; j++){
                    float p = kval[nf][j] ? __expf(S[nf][i*2+j] - mn) : 0.f;
                    S[nf][i*2+j] = p;
                    ssum += p;
                }
            }
            ssum += __shfl_xor_sync(0xffffffffu, ssum, 1);
            ssum += __shfl_xor_sync(0xffffffffu, ssum, 2);
            li[i] = li[i]*alpha[i] + ssum;
            mi[i] = mn;
        }
        // rescale O
#pragma unroll
        for (int nf = 0; nf < 8; nf++){
            O[nf][0] *= alpha[0]; O[nf][1] *= alpha[0];
            O[nf][2] *= alpha[1]; O[nf][3] *= alpha[1];
        }
        // write P to smem (warp-private rows)
#pragma unroll
        for (int nf = 0; nf < 8; nf++){
#pragma unroll
            for (int i = 0; i < 2; i++){
                int r = w*16 + (lane >> 2) + i*8;
                int c = nf*8 + (lane & 3)*2;
                Ps[r*68 + c]     = f2tf(S[nf][i*2]);
                Ps[r*68 + c + 1] = f2tf(S[nf][i*2+1]);
            }
        }
        __syncwarp();

        // O += P V
#pragma unroll
        for (int kf = 0; kf < 8; kf++){
            int kc = kf*8 + (lane & 3);
            int rbase = w*16 + (lane >> 2);
            unsigned a0 = Ps[(rbase    )*68 + kc    ];
            unsigned a1 = Ps[(rbase + 8)*68 + kc    ];
            unsigned a2 = Ps[(rbase    )*68 + kc + 4];
            unsigned a3 = Ps[(rbase + 8)*68 + kc + 4];
#pragma unroll
            for (int nf = 0; nf < 8; nf++){
                unsigned b0 = Vs[(kf*8 + (lane & 3)    )*72 + nf*8 + (lane >> 2)];
                unsigned b1 = Vs[(kf*8 + (lane & 3) + 4)*72 + nf*8 + (lane >> 2)];
                mma_tf32(O[nf][0], O[nf][1], O[nf][2], O[nf][3], a0, a1, a2, a3, b0, b1);
            }
        }
    }

    // epilogue
#pragma unroll
    for (int i = 0; i < 2; i++){
        int qn = q0 + w*16 + (lane >> 2) + i*8;
        if (qn >= CN) continue;
        float invl = 1.f / li[i];
        size_t base = ((size_t)b*CN + qn)*CC + h*64;
#pragma unroll
        for (int nf = 0; nf < 8; nf++){
            int c = nf*8 + (lane & 3)*2;
            *(float2*)(ao + base + c) = make_float2(O[nf][i*2]*invl, O[nf][i*2+1]*invl);
        }
    }
}

// ---------------- final: out = fused + BN(op_pw output), with transpose ----------------
__global__ void k_final(const float* __restrict__ fused, const float* __restrict__ o2t,
                        const float* __restrict__ bn, float* __restrict__ out)
{
    __shared__ float tile[32][33];
    int b = blockIdx.z;
    int p0 = blockIdx.x * 32, c0 = blockIdx.y * 32;
    int tx = threadIdx.x, ty = threadIdx.y;
#pragma unroll
    for (int i = 0; i < 4; i++){
        int p = p0 + ty + i*8;
        tile[ty + i*8][tx] = o2t[((size_t)b*CHW + p)*CC + c0 + tx];
    }
    __syncthreads();
#pragma unroll
    for (int i = 0; i < 4; i++){
        int c = c0 + ty + i*8;
        float s = bn[c] * rsqrtf(bn[3*CC+c] + EPS);
        float t = bn[CC+c] - bn[2*CC+c] * s;
        size_t idx = ((size_t)b*CC + c)*CHW + p0 + tx;
        out[idx] = fused[idx] + tile[tx][ty + i*8] * s + t;
    }
}

// ---------------- host ----------------
static void launch_gemm(int epi, const float* A, const float* Bw, float* Cm,
                        int M, int N, int K, const float* ep, const float* res)
{
    dim3 g(N/128, (M + 127)/128);
    switch (epi){
        case 0: k_gemm_tc<0><<<g,256>>>(A,Bw,Cm,M,N,K,ep,res); break;
        case 1: k_gemm_tc<1><<<g,256>>>(A,Bw,Cm,M,N,K,ep,res); break;
        case 2: k_gemm_tc<2><<<g,256>>>(A,Bw,Cm,M,N,K,ep,res); break;
        case 3: k_gemm_tc<3><<<g,256>>>(A,Bw,Cm,M,N,K,ep,res); break;
        case 4: k_gemm_tc<4><<<g,256>>>(A,Bw,Cm,M,N,K,ep,res); break;
    }
}

extern "C" void kernel_launch(void* const* d_in, const int* in_sizes, int n_in,
                              void* d_out, int out_size)
{
    const float* fused        = (const float*)d_in[0];
    const float* depth        = (const float*)d_in[1];
    const float* pg_dw_w      = (const float*)d_in[2];
    const float* pg_bn1       = (const float*)d_in[3];
    const float* pg_pw_w      = (const float*)d_in[4];
    const float* pg_bn2       = (const float*)d_in[5];
    const float* prompt_embed = (const float*)d_in[6];
    const float* pg_ln        = (const float*)d_in[7];
    const float* gp_dw_w      = (const float*)d_in[8];
    const float* gp_bn        = (const float*)d_in[9];
    const float* gp_pw_w      = (const float*)d_in[10];
    const float* gp_pw_b      = (const float*)d_in[11];
    const float* gp_weight    = (const float*)d_in[12];
    const float* ln1          = (const float*)d_in[13];
    const float* wq           = (const float*)d_in[14];
    const float* wk           = (const float*)d_in[15];
    const float* wv           = (const float*)d_in[16];
    const float* wo           = (const float*)d_in[17];
    const float* ln2          = (const float*)d_in[18];
    const float* mlp_w1       = (const float*)d_in[19];
    const float* mlp_b1       = (const float*)d_in[20];
    const float* mlp_w2       = (const float*)d_in[21];
    const float* mlp_b2       = (const float*)d_in[22];
    const float* op_dw_w      = (const float*)d_in[23];
    const float* op_bn1       = (const float*)d_in[24];
    const float* op_pw_w      = (const float*)d_in[25];
    const float* op_bn2       = (const float*)d_in[26];

    float *dw1,*dsf,*pp1t,*pp2t,*ds,*prm,*jdb,*jt,*xb,*qb,*kb,*vb,*aob,*hb,*enh,*o1c,*o1t,*o2t;
    cudaGetSymbolAddress((void**)&dw1,  g_dw1);
    cudaGetSymbolAddress((void**)&dsf,  g_dsf);
    cudaGetSymbolAddress((void**)&pp1t, g_pp1t);
    cudaGetSymbolAddress((void**)&pp2t, g_pp2t);
    cudaGetSymbolAddress((void**)&ds,   g_ds);
    cudaGetSymbolAddress((void**)&prm,  g_prompt);
    cudaGetSymbolAddress((void**)&jdb,  g_jd);
    cudaGetSymbolAddress((void**)&jt,   g_jt);
    cudaGetSymbolAddress((void**)&xb,   g_x);
    cudaGetSymbolAddress((void**)&qb,   g_q);
    cudaGetSymbolAddress((void**)&kb,   g_k);
    cudaGetSymbolAddress((void**)&vb,   g_v);
    cudaGetSymbolAddress((void**)&aob,  g_ao);
    cudaGetSymbolAddress((void**)&hb,   g_h);
    cudaGetSymbolAddress((void**)&enh,  g_enh);
    cudaGetSymbolAddress((void**)&o1c,  g_o1c);
    cudaGetSymbolAddress((void**)&o1t,  g_o1t);
    cudaGetSymbolAddress((void**)&o2t,  g_o2t);

    cudaFuncSetAttribute(k_attn, cudaFuncAttributeMaxDynamicSharedMemorySize, ATTN_SMEM);

    dim3 tgrid(CHW/32, CC/32, CB), tblk(32, 8);

    // --- DepthPromptGenerator + GeometryPriorGenerator shared dwconv ---
    k_dwconv_dual<<<(CB*CC*CHW)/256, 256>>>(depth, pg_dw_w, pg_bn1, dw1, gp_dw_w, gp_bn, dsf);
    k_cp_to_tok<<<tgrid, tblk>>>(dw1, pp1t, CHW, 0);
    launch_gemm(1, pp1t, pg_pw_w, pp2t, CB*CHW, CC, CC, pg_bn2, nullptr);   // bn2 + gelu
    k_gp_pw<<<(CB*CHW)/32, 256>>>(dsf, gp_pw_w, gp_pw_b, ds);
    k_prompt<<<CB*NPR, 256>>>(pp2t, prompt_embed, pg_ln, prm);
    k_jd<<<(CB*CN + 255)/256, 256>>>(ds, jdb);

    // --- assemble joint tokens ---
    k_copy_prompt<<<(CB*NPR*CC)/256, 256>>>(prm, jt);
    k_cp_to_tok<<<tgrid, tblk>>>(fused, jt, CN, NPR);

    // --- attention block ---
    k_ln<<<CB*CN, 256>>>(jt, ln1, xb);
    launch_gemm(0, xb, wq, qb, CB*CN, CC, CC, nullptr, nullptr);
    launch_gemm(0, xb, wk, kb, CB*CN, CC, CC, nullptr, nullptr);
    launch_gemm(0, xb, wv, vb, CB*CN, CC, CC, nullptr, nullptr);
    k_attn<<<dim3(9, CNH, CB), 256, ATTN_SMEM>>>(qb, kb, vb, jdb, gp_weight, aob);
    launch_gemm(4, aob, wo, jt, CB*CN, CC, CC, nullptr, jt);                // jt += ao@wo^T

    // --- MLP ---
    k_ln<<<CB*CN, 256>>>(jt, ln2, xb);
    launch_gemm(2, xb, mlp_w1, hb, CB*CN, HID, CC, mlp_b1, nullptr);        // bias + gelu
    launch_gemm(3, hb, mlp_w2, jt, CB*CN, CC, HID, mlp_b2, jt);             // bias + residual

    // --- out_proj ---
    k_tok_to_cp<<<tgrid, tblk>>>(jt, enh, CN, NPR);
    k_dwconv_dual<<<(CB*CC*CHW)/256, 256>>>(enh, op_dw_w, op_bn1, o1c, nullptr, nullptr, nullptr);
    k_cp_to_tok<<<tgrid, tblk>>>(o1c, o1t, CHW, 0);
    launch_gemm(0, o1t, op_pw_w, o2t, CB*CHW, CC, CC, nullptr, nullptr);
    k_final<<<tgrid, tblk>>>(fused, o2t, op_bn2, (float*)d_out);
}

// round 6
// speedup vs baseline: 1.3642x; 1.3642x over previous
#include <cuda_runtime.h>
#include <cuda_bf16.h>
#include <math.h>

// ---------------- problem constants ----------------
constexpr int CB  = 4;      // batch
constexpr int CC  = 512;    // channels
constexpr int CHH = 32;     // H
constexpr int CWW = 32;     // W
constexpr int CHW = 1024;   // H*W
constexpr int CNH = 8;      // heads
constexpr int NPR = 8;      // prompt tokens
constexpr int CN  = 1032;   // total tokens
constexpr int HID = 1024;   // mlp hidden
constexpr int QKV = 3*CC;   // fused qkv row stride
constexpr float EPS = 1e-5f;

// ---------------- scratch (static device memory; no allocations) ----------------
__device__ __align__(16) float g_dw1 [CB*CC*CHW];
__device__ __align__(16) float g_dsf [CB*CC*CHW];
__device__ __align__(16) float g_pp1t[CB*CHW*CC];
__device__ __align__(16) float g_pp2t[CB*CHW*CC];
__device__ __align__(16) float g_ds  [CB*CHW];
__device__ __align__(16) float g_prompt[CB*NPR*CC];
__device__ __align__(16) float g_jd  [CB*CN];
__device__ __align__(16) float g_jt  [CB*CN*CC];
__device__ __align__(16) float g_x   [CB*CN*CC];
__device__ __align__(16) float g_wqkv[QKV*CC];
__device__ __align__(16) float g_qkv [CB*CN*QKV];
__device__ __align__(16) float g_ao  [CB*CN*CC];
__device__ __align__(16) float g_h   [CB*CN*HID];
__device__ __align__(16) float g_enh [CB*CC*CHW];
__device__ __align__(16) float g_o1c [CB*CC*CHW];
__device__ __align__(16) float g_o1t [CB*CHW*CC];
__device__ __align__(16) float g_o2t [CB*CHW*CC];

__device__ __forceinline__ float gelu_f(float x){
    return 0.5f * x * (1.0f + erff(x * 0.70710678118654752f));
}

// pack two f32 into bf16x2 (lo in low half, hi in high half)
__device__ __forceinline__ unsigned pack_bf(float lo, float hi){
    unsigned r;
    asm("cvt.rn.bf16x2.f32 %0, %1, %2;" : "=r"(r) : "f"(hi), "f"(lo));
    return r;
}

__device__ __forceinline__ void mma_bf16(float& d0, float& d1, float& d2, float& d3,
                                         unsigned a0, unsigned a1, unsigned a2, unsigned a3,
                                         unsigned b0, unsigned b1)
{
    asm volatile("mma.sync.aligned.m16n8k16.row.col.f32.bf16.bf16.f32 "
                 "{%0,%1,%2,%3}, {%4,%5,%6,%7}, {%8,%9}, {%0,%1,%2,%3};"
                 : "+f"(d0), "+f"(d1), "+f"(d2), "+f"(d3)
                 : "r"(a0), "r"(a1), "r"(a2), "r"(a3), "r"(b0), "r"(b1));
}

// ---------------- depthwise 3x3 conv + BN + GELU (optionally two branches) ----------------
__global__ void k_dwconv_dual(const float* __restrict__ in,
                              const float* __restrict__ w1, const float* __restrict__ bn1,
                              float* __restrict__ out1,
                              const float* __restrict__ w2, const float* __restrict__ bn2,
                              float* __restrict__ out2)
{
    int idx = blockIdx.x * 256 + threadIdx.x;
    if (idx >= CB*CC*CHW) return;
    int p = idx & (CHW-1);
    int c = (idx >> 10) & (CC-1);
    int y = p >> 5, x = p & 31;
    const float* base = in + (size_t)(idx - p);
    float v[9];
#pragma unroll
    for (int ky = 0; ky < 3; ky++)
#pragma unroll
        for (int kx = 0; kx < 3; kx++){
            int yy = y + ky - 1, xx = x + kx - 1;
            v[ky*3+kx] = (yy >= 0 && yy < CHH && xx >= 0 && xx < CWW) ? base[yy*CWW + xx] : 0.f;
        }
    {
        float a = 0.f;
#pragma unroll
        for (int k = 0; k < 9; k++) a += w1[c*9+k] * v[k];
        float s = bn1[c] * rsqrtf(bn1[3*CC+c] + EPS);
        a = a * s + bn1[CC+c] - bn1[2*CC+c] * s;
        out1[idx] = gelu_f(a);
    }
    if (out2){
        float a = 0.f;
#pragma unroll
        for (int k = 0; k < 9; k++) a += w2[c*9+k] * v[k];
        float s = bn2[c] * rsqrtf(bn2[3*CC+c] + EPS);
        a = a * s + bn2[CC+c] - bn2[2*CC+c] * s;
        out2[idx] = gelu_f(a);
    }
}

// ---------------- transposes ----------------
__global__ void k_cp_to_tok(const float* __restrict__ in, float* __restrict__ out,
                            int tokTotal, int tokOff)
{
    __shared__ float tile[32][33];
    int b = blockIdx.z;
    int p0 = blockIdx.x * 32, c0 = blockIdx.y * 32;
    int tx = threadIdx.x, ty = threadIdx.y;
#pragma unroll
    for (int i = 0; i < 4; i++){
        int c = c0 + ty + i*8;
        tile[ty + i*8][tx] = in[((size_t)b*CC + c)*CHW + p0 + tx];
    }
    __syncthreads();
#pragma unroll
    for (int i = 0; i < 4; i++){
        int p = p0 + ty + i*8;
        out[((size_t)b*tokTotal + tokOff + p)*CC + c0 + tx] = tile[tx][ty + i*8];
    }
}

__global__ void k_tok_to_cp(const float* __restrict__ in, float* __restrict__ out,
                            int tokTotal, int tokOff)
{
    __shared__ float tile[32][33];
    int b = blockIdx.z;
    int p0 = blockIdx.x * 32, c0 = blockIdx.y * 32;
    int tx = threadIdx.x, ty = threadIdx.y;
#pragma unroll
    for (int i = 0; i < 4; i++){
        int p = p0 + ty + i*8;
        tile[ty + i*8][tx] = in[((size_t)b*tokTotal + tokOff + p)*CC + c0 + tx];
    }
    __syncthreads();
#pragma unroll
    for (int i = 0; i < 4; i++){
        int c = c0 + ty + i*8;
        out[((size_t)b*CC + c)*CHW + p0 + tx] = tile[tx][ty + i*8];
    }
}

// ---------------- tensor-core NT GEMM (bf16 m16n8k16), 128x128 tile, K-chunk 32 ----------------
// C[m,n] = sum_k A[m,k]*B[n,k].  EPI: 0 plain, 1 bn+gelu, 2 bias+gelu, 3 bias+res, 4 res
constexpr int GSTU = 12;        // uint stride per 16-k sub-tile row (12 mod 32 = 12 -> rows land on 4-spaced banks)
constexpr int ASUB = 128*GSTU;  // uints per 16-k sub-tile

template<int EPI>
__global__ void __launch_bounds__(256) k_gemm_bf(const float* __restrict__ A,
                                                 const float* __restrict__ Bw,
                                                 float* __restrict__ Cmat,
                                                 int M, int N, int K,
                                                 const float* __restrict__ ep,
                                                 const float* __restrict__ res)
{
    __shared__ unsigned As[2][2*ASUB];
    __shared__ unsigned Bs[2][2*ASUB];

    int tid  = threadIdx.x;
    int lane = tid & 31;
    int w    = tid >> 5;
    int wm   = w >> 1;         // 0..3 (M)
    int wn   = w & 1;          // 0..1 (N)
    int m0 = blockIdx.y * 128, n0 = blockIdx.x * 128;

    // per-stage loads: 128 rows x 32 floats per matrix = 1024 float4; 4 per thread
    int rr[4], fc[4], so[4];
#pragma unroll
    for (int s = 0; s < 4; s++){
        int i = tid + 256*s;
        rr[s] = i >> 3;              // row 0..127
        fc[s] = (i & 7) * 4;         // float col 0..28
        so[s] = ((i >> 2) & 1) * ASUB + rr[s]*GSTU + (i & 3)*2;  // smem uint offset
    }

    float acc[2][8][4];
#pragma unroll
    for (int mf = 0; mf < 2; mf++)
#pragma unroll
        for (int nf = 0; nf < 8; nf++)
#pragma unroll
            for (int r = 0; r < 4; r++) acc[mf][nf][r] = 0.f;

    int NK = K >> 5;

    // prologue
#pragma unroll
    for (int s = 0; s < 4; s++){
        float4 a = (m0 + rr[s] < M) ? *(const float4*)(A + (size_t)(m0 + rr[s])*K + fc[s]) : make_float4(0,0,0,0);
        float4 b = *(const float4*)(Bw + (size_t)(n0 + rr[s])*K + fc[s]);
        *(uint2*)&As[0][so[s]] = make_uint2(pack_bf(a.x, a.y), pack_bf(a.z, a.w));
        *(uint2*)&Bs[0][so[s]] = make_uint2(pack_bf(b.x, b.y), pack_bf(b.z, b.w));
    }
    __syncthreads();

    for (int kt = 0; kt < NK; kt++){
        float4 pa[4], pb[4];
        bool has_next = (kt + 1 < NK);
        if (has_next){
            int kb = (kt + 1) << 5;
#pragma unroll
            for (int s = 0; s < 4; s++){
                pa[s] = (m0 + rr[s] < M) ? *(const float4*)(A + (size_t)(m0 + rr[s])*K + kb + fc[s]) : make_float4(0,0,0,0);
                pb[s] = *(const float4*)(Bw + (size_t)(n0 + rr[s])*K + kb + fc[s]);
            }
        }
        const unsigned* Abuf = As[kt & 1];
        const unsigned* Bbuf = Bs[kt & 1];
        int c = lane & 3;
        int gr = lane >> 2;
#pragma unroll
        for (int kf = 0; kf < 2; kf++){
            const unsigned* Ac = Abuf + kf*ASUB;
            const unsigned* Bc = Bbuf + kf*ASUB;
            unsigned afr[2][4];
#pragma unroll
            for (int mf = 0; mf < 2; mf++){
                int rbase = wm*32 + mf*16 + gr;
                afr[mf][0] = Ac[(rbase    )*GSTU + c    ];
                afr[mf][1] = Ac[(rbase + 8)*GSTU + c    ];
                afr[mf][2] = Ac[(rbase    )*GSTU + c + 4];
                afr[mf][3] = Ac[(rbase + 8)*GSTU + c + 4];
            }
#pragma unroll
            for (int nf = 0; nf < 8; nf++){
                int nb = wn*64 + nf*8 + gr;
                unsigned b0 = Bc[nb*GSTU + c];
                unsigned b1 = Bc[nb*GSTU + c + 4];
#pragma unroll
                for (int mf = 0; mf < 2; mf++)
                    mma_bf16(acc[mf][nf][0], acc[mf][nf][1], acc[mf][nf][2], acc[mf][nf][3],
                             afr[mf][0], afr[mf][1], afr[mf][2], afr[mf][3], b0, b1);
            }
        }
        if (has_next){
            unsigned bi = (kt + 1) & 1;
#pragma unroll
            for (int s = 0; s < 4; s++){
                *(uint2*)&As[bi][so[s]] = make_uint2(pack_bf(pa[s].x, pa[s].y), pack_bf(pa[s].z, pa[s].w));
                *(uint2*)&Bs[bi][so[s]] = make_uint2(pack_bf(pb[s].x, pb[s].y), pack_bf(pb[s].z, pb[s].w));
            }
        }
        __syncthreads();
    }

    // epilogue
#pragma unroll
    for (int mf = 0; mf < 2; mf++){
#pragma unroll
        for (int ri = 0; ri < 2; ri++){
            int row = m0 + wm*32 + mf*16 + (lane >> 2) + ri*8;
            if (row >= M) continue;
            size_t base = (size_t)row * N;
#pragma unroll
            for (int nf = 0; nf < 8; nf++){
                int col = n0 + wn*64 + nf*8 + 2*(lane & 3);
                float v0 = acc[mf][nf][ri*2 + 0];
                float v1 = acc[mf][nf][ri*2 + 1];
                if (EPI == 1){
                    float s0 = ep[col]   * rsqrtf(ep[3*N+col]   + EPS);
                    float s1 = ep[col+1] * rsqrtf(ep[3*N+col+1] + EPS);
                    v0 = gelu_f(v0 * s0 + ep[N+col]   - ep[2*N+col]   * s0);
                    v1 = gelu_f(v1 * s1 + ep[N+col+1] - ep[2*N+col+1] * s1);
                } else if (EPI == 2){
                    v0 = gelu_f(v0 + ep[col]);
                    v1 = gelu_f(v1 + ep[col+1]);
                } else if (EPI == 3){
                    float2 rr2 = *(const float2*)(res + base + col);
                    v0 = rr2.x + v0 + ep[col];
                    v1 = rr2.y + v1 + ep[col+1];
                } else if (EPI == 4){
                    float2 rr2 = *(const float2*)(res + base + col);
                    v0 = rr2.x + v0;
                    v1 = rr2.y + v1;
                }
                *(float2*)(Cmat + base + col) = make_float2(v0, v1);
            }
        }
    }
}

// ---------------- geometry prior: 512->1 projection (parallel) ----------------
__global__ void k_gp_pw(const float* __restrict__ dsf, const float* __restrict__ w,
                        const float* __restrict__ bias, float* __restrict__ ds)
{
    __shared__ float red[8][33];
    int px = threadIdx.x & 31;
    int cz = threadIdx.x >> 5;
    int p0 = blockIdx.x * 32;
    int b  = p0 >> 10;
    int p  = (p0 & (CHW-1)) + px;
    float acc = 0.f;
#pragma unroll
    for (int i = 0; i < 64; i++){
        int c = cz*64 + i;
        acc += w[c] * dsf[((size_t)b*CC + c)*CHW + p];
    }
    red[cz][px] = acc;
    __syncthreads();
    if (cz == 0){
        float s = 0.f;
#pragma unroll
        for (int z = 0; z < 8; z++) s += red[z][px];
        ds[p0 + px] = s + bias[0];
    }
}

// ---------------- prompt: pool + embed + LN ----------------
__global__ void k_prompt(const float* __restrict__ pp2t, const float* __restrict__ pe,
                         const float* __restrict__ lnp, float* __restrict__ out)
{
    int b = blockIdx.x >> 3, pr = blockIdx.x & 7;
    int iy = pr >> 2, ix = pr & 3;
    int t = threadIdx.x;
    float a0 = 0.f, a1 = 0.f;
    for (int py = 0; py < 16; py++)
        for (int px = 0; px < 8; px++){
            int p = (iy*16 + py)*CWW + ix*8 + px;
            const float* base = pp2t + ((size_t)b*CHW + p)*CC;
            a0 += base[t];
            a1 += base[t + 256];
        }
    a0 = a0 * (1.f/128.f) + pe[pr*CC + t];
    a1 = a1 * (1.f/128.f) + pe[pr*CC + t + 256];
    __shared__ float rs[256], rq[256];
    rs[t] = a0 + a1; rq[t] = a0*a0 + a1*a1;
    __syncthreads();
    for (int s = 128; s > 0; s >>= 1){
        if (t < s){ rs[t] += rs[t+s]; rq[t] += rq[t+s]; }
        __syncthreads();
    }
    float mean = rs[0] * (1.f/512.f);
    float var  = rq[0] * (1.f/512.f) - mean*mean;
    float inv  = rsqrtf(var + EPS);
    size_t o = ((size_t)b*NPR + pr) * CC;
    out[o + t]       = (a0 - mean) * inv * lnp[t]       + lnp[CC + t];
    out[o + t + 256] = (a1 - mean) * inv * lnp[t + 256] + lnp[CC + t + 256];
}

// ---------------- joint depth scalar per token ----------------
__global__ void k_jd(const float* __restrict__ ds, float* __restrict__ jd)
{
    int t = blockIdx.x * 256 + threadIdx.x;
    if (t >= CB*CN) return;
    int b = t / CN, n = t % CN;
    if (n >= NPR){
        jd[t] = ds[b*CHW + (n - NPR)];
    } else {
        int iy = n >> 2, ix = n & 3;
        float acc = 0.f;
        for (int py = 0; py < 16; py++)
            for (int px = 0; px < 8; px++)
                acc += ds[b*CHW + (iy*16 + py)*CWW + ix*8 + px];
        jd[t] = acc * (1.f/128.f);
    }
}

// ---------------- copy prompt tokens into jt ----------------
__global__ void k_copy_prompt(const float* __restrict__ pr, float* __restrict__ jt)
{
    int idx = blockIdx.x * 256 + threadIdx.x;
    if (idx >= CB*NPR*CC) return;
    int b = idx / (NPR*CC), r = idx % (NPR*CC);
    jt[(size_t)b*CN*CC + r] = pr[(size_t)b*NPR*CC + r];
}

// ---------------- layernorm over C per token ----------------
__global__ void k_ln(const float* __restrict__ in, const float* __restrict__ p,
                     float* __restrict__ out)
{
    int tok = blockIdx.x;
    const float* row = in + (size_t)tok * CC;
    int t = threadIdx.x;
    float v0 = row[t], v1 = row[t + 256];
    __shared__ float rs[256], rq[256];
    rs[t] = v0 + v1; rq[t] = v0*v0 + v1*v1;
    __syncthreads();
    for (int s = 128; s > 0; s >>= 1){
        if (t < s){ rs[t] += rs[t+s]; rq[t] += rq[t+s]; }
        __syncthreads();
    }
    float mean = rs[0] * (1.f/512.f);
    float var  = rq[0] * (1.f/512.f) - mean*mean;
    float inv  = rsqrtf(var + EPS);
    size_t o = (size_t)tok * CC;
    out[o + t]       = (v0 - mean) * inv * p[t]       + p[CC + t];
    out[o + t + 256] = (v1 - mean) * inv * p[t + 256] + p[CC + t + 256];
}

// ---------------- attention: flash-style, bf16 mma, analytic bias ----------------
__device__ __forceinline__ void tok_coord(int n, float& cy, float& cx){
    if (n < NPR){ cy = (float)(n >> 2); cx = (float)(n & 3) * (1.f/3.f); }
    else { int m = n - NPR; cy = (float)(m >> 5) * (1.f/31.f); cx = (float)(m & 31) * (1.f/31.f); }
}

constexpr int AST = 36;                      // uint stride for 64-bf16 rows (36 mod 32 = 4)
constexpr int QS_OFF = 0;                    // 128 rows
constexpr int KS_OFF = QS_OFF + 128*AST;     // 64 rows
constexpr int VS_OFF = KS_OFF + 64*AST;      // 64 rows (transposed: rows = d)
constexpr int PS_OFF = VS_OFF + 64*AST;      // 128 rows
constexpr int KD_OFF = PS_OFF + 128*AST;     // 64 floats
constexpr int ATTN_SMEM = (KD_OFF + 64) * 4; // bytes

__global__ void __launch_bounds__(256) k_attn(const float* __restrict__ qkv,
                                              const float* __restrict__ jd,
                                              const float* __restrict__ gw,
                                              float* __restrict__ ao)
{
    extern __shared__ unsigned smu[];
    unsigned* Qs = smu + QS_OFF;
    unsigned* Ks = smu + KS_OFF;
    unsigned* Vt = smu + VS_OFF;
    unsigned* Ps = smu + PS_OFF;
    float*  kdep = (float*)(smu + KD_OFF);
    __nv_bfloat16* Vt16 = (__nv_bfloat16*)Vt;

    int b = blockIdx.z, h = blockIdx.y, q0 = blockIdx.x * 128;
    int tid = threadIdx.x, lane = tid & 31, w = tid >> 5;
    int c = lane & 3, gr = lane >> 2;

    const float decay = logf(1.f - exp2f(-1.f - 0.5f * (float)h));
    const float w0 = gw[0] * decay, w1 = gw[1] * decay;

    // load Q tile (128 x 64) -> bf16 rows, stride AST uints
#pragma unroll
    for (int j = 0; j < 8; j++){
        int i = tid + 256*j;
        int r = i >> 4, c4 = (i & 15) * 4;
        int qn = q0 + r;
        float4 v = (qn < CN) ? *(const float4*)(qkv + ((size_t)b*CN + qn)*QKV + h*64 + c4)
                             : make_float4(0,0,0,0);
        *(uint2*)&Qs[r*AST + (i & 15)*2] = make_uint2(pack_bf(v.x, v.y), pack_bf(v.z, v.w));
    }

    // q-row metadata (2 rows per thread)
    float qy[2], qx[2], qd[2];
#pragma unroll
    for (int i = 0; i < 2; i++){
        int qn = q0 + w*16 + gr + i*8;
        if (qn < CN){ tok_coord(qn, qy[i], qx[i]); qd[i] = jd[b*CN + qn]; }
        else { qy[i] = qx[i] = qd[i] = 0.f; }
    }

    float O[8][4];
#pragma unroll
    for (int nf = 0; nf < 8; nf++)
#pragma unroll
        for (int r = 0; r < 4; r++) O[nf][r] = 0.f;
    float mi[2] = {-1e30f, -1e30f}, li[2] = {0.f, 0.f};

    for (int kt = 0; kt < 17; kt++){
        int k0 = kt * 64;
        __syncthreads();   // previous tile fully consumed
        // load K (rows = key) and V transposed (rows = d)
#pragma unroll
        for (int j = 0; j < 4; j++){
            int i = tid + 256*j;
            int r = i >> 4, c4 = (i & 15) * 4;
            int n = k0 + r;
            bool val = (n < CN);
            const float* rowp = qkv + ((size_t)b*CN + n)*QKV + h*64;
            float4 kv = val ? *(const float4*)(rowp + CC  + c4) : make_float4(0,0,0,0);
            float4 vv = val ? *(const float4*)(rowp + 2*CC + c4) : make_float4(0,0,0,0);
            *(uint2*)&Ks[r*AST + (i & 15)*2] = make_uint2(pack_bf(kv.x, kv.y), pack_bf(kv.z, kv.w));
            Vt16[(c4+0)*(AST*2) + r] = __float2bfloat16(vv.x);
            Vt16[(c4+1)*(AST*2) + r] = __float2bfloat16(vv.y);
            Vt16[(c4+2)*(AST*2) + r] = __float2bfloat16(vv.z);
            Vt16[(c4+3)*(AST*2) + r] = __float2bfloat16(vv.w);
        }
        if (tid < 64) kdep[tid] = (k0 + tid < CN) ? jd[b*CN + k0 + tid] : 0.f;
        __syncthreads();

        // S = Q K^T (warp computes its 16 rows x 64 cols), K=64 -> 4 k16 steps
        float S[8][4];
#pragma unroll
        for (int nf = 0; nf < 8; nf++)
#pragma unroll
            for (int r = 0; r < 4; r++) S[nf][r] = 0.f;
        int rbase = w*16 + gr;
#pragma unroll
        for (int kf = 0; kf < 4; kf++){
            int kc = kf*8 + c;
            unsigned a0 = Qs[(rbase    )*AST + kc    ];
            unsigned a1 = Qs[(rbase + 8)*AST + kc    ];
            unsigned a2 = Qs[(rbase    )*AST + kc + 4];
            unsigned a3 = Qs[(rbase + 8)*AST + kc + 4];
#pragma unroll
            for (int nf = 0; nf < 8; nf++){
                int nb = nf*8 + gr;
                unsigned b0 = Ks[nb*AST + kc];
                unsigned b1 = Ks[nb*AST + kc + 4];
                mma_bf16(S[nf][0], S[nf][1], S[nf][2], S[nf][3], a0, a1, a2, a3, b0, b1);
            }
        }

        // bias + scale, validity
        bool kval[8][2];
#pragma unroll
        for (int nf = 0; nf < 8; nf++){
#pragma unroll
            for (int j = 0; j < 2; j++){
                int kl = nf*8 + c*2 + j;
                int kn = k0 + kl;
                kval[nf][j] = (kn < CN);
                float ky, kx;
                tok_coord(kn, ky, kx);
                float kd = kdep[kl];
#pragma unroll
                for (int i = 0; i < 2; i++){
                    float pos = fabsf(qy[i]-ky) + fabsf(qx[i]-kx);
                    float vv = S[nf][i*2+j]*0.125f + w0*pos + w1*fabsf(qd[i]-kd);
                    S[nf][i*2+j] = kval[nf][j] ? vv : -1e30f;
                }
            }
        }

        // online softmax per row (quad reduction)
        float alpha[2];
#pragma unroll
        for (int i = 0; i < 2; i++){
            float tm = -1e30f;
#pragma unroll
            for (int nf = 0; nf < 8; nf++){
                tm = fmaxf(tm, S[nf][i*2]);
                tm = fmaxf(tm, S[nf][i*2+1]);
            }
            tm = fmaxf(tm, __shfl_xor_sync(0xffffffffu, tm, 1));
            tm = fmaxf(tm, __shfl_xor_sync(0xffffffffu, tm, 2));
            float mn = fmaxf(mi[i], tm);
            alpha[i] = __expf(mi[i] - mn);
            float ssum = 0.f;
#pragma unroll
            for (int nf = 0; nf < 8; nf++){
#pragma unroll
                for (int j = 0; j < 2; j++){
                    float p = kval[nf][j] ? __expf(S[nf][i*2+j] - mn) : 0.f;
                    S[nf][i*2+j] = p;
                    ssum += p;
                }
            }
            ssum += __shfl_xor_sync(0xffffffffu, ssum, 1);
            ssum += __shfl_xor_sync(0xffffffffu, ssum, 2);
            li[i] = li[i]*alpha[i] + ssum;
            mi[i] = mn;
        }
#pragma unroll
        for (int nf = 0; nf < 8; nf++){
            O[nf][0] *= alpha[0]; O[nf][1] *= alpha[0];
            O[nf][2] *= alpha[1]; O[nf][3] *= alpha[1];
        }
        // write P to smem as bf16 pairs (warp-private rows)
#pragma unroll
        for (int nf = 0; nf < 8; nf++){
#pragma unroll
            for (int i = 0; i < 2; i++){
                int r = rbase + i*8;
                Ps[r*AST + nf*4 + c] = pack_bf(S[nf][i*2], S[nf][i*2+1]);
            }
        }
        __syncwarp();

        // O += P V  (P: 16 x 64 keys; Vt rows = d)
#pragma unroll
        for (int kf = 0; kf < 4; kf++){
            int kc = kf*8 + c;
            unsigned a0 = Ps[(rbase    )*AST + kc    ];
            unsigned a1 = Ps[(rbase + 8)*AST + kc    ];
            unsigned a2 = Ps[(rbase    )*AST + kc + 4];
            unsigned a3 = Ps[(rbase + 8)*AST + kc + 4];
#pragma unroll
            for (int nf = 0; nf < 8; nf++){
                int d = nf*8 + gr;
                unsigned b0 = Vt[d*AST + kc];
                unsigned b1 = Vt[d*AST + kc + 4];
                mma_bf16(O[nf][0], O[nf][1], O[nf][2], O[nf][3], a0, a1, a2, a3, b0, b1);
            }
        }
    }

    // epilogue
#pragma unroll
    for (int i = 0; i < 2; i++){
        int qn = q0 + w*16 + gr + i*8;
        if (qn >= CN) continue;
        float invl = 1.f / li[i];
        size_t base = ((size_t)b*CN + qn)*CC + h*64;
#pragma unroll
        for (int nf = 0; nf < 8; nf++){
            int cc2 = nf*8 + c*2;
            *(float2*)(ao + base + cc2) = make_float2(O[nf][i*2]*invl, O[nf][i*2+1]*invl);
        }
    }
}

// ---------------- final: out = fused + BN(op_pw output), with transpose ----------------
__global__ void k_final(const float* __restrict__ fused, const float* __restrict__ o2t,
                        const float* __restrict__ bn, float* __restrict__ out)
{
    __shared__ float tile[32][33];
    int b = blockIdx.z;
    int p0 = blockIdx.x * 32, c0 = blockIdx.y * 32;
    int tx = threadIdx.x, ty = threadIdx.y;
#pragma unroll
    for (int i = 0; i < 4; i++){
        int p = p0 + ty + i*8;
        tile[ty + i*8][tx] = o2t[((size_t)b*CHW + p)*CC + c0 + tx];
    }
    __syncthreads();
#pragma unroll
    for (int i = 0; i < 4; i++){
        int c = c0 + ty + i*8;
        float s = bn[c] * rsqrtf(bn[3*CC+c] + EPS);
        float t = bn[CC+c] - bn[2*CC+c] * s;
        size_t idx = ((size_t)b*CC + c)*CHW + p0 + tx;
        out[idx] = fused[idx] + tile[tx][ty + i*8] * s + t;
    }
}

// ---------------- host ----------------
static void launch_gemm(int epi, const float* A, const float* Bw, float* Cm,
                        int M, int N, int K, const float* ep, const float* res)
{
    dim3 g(N/128, (M + 127)/128);
    switch (epi){
        case 0: k_gemm_bf<0><<<g,256>>>(A,Bw,Cm,M,N,K,ep,res); break;
        case 1: k_gemm_bf<1><<<g,256>>>(A,Bw,Cm,M,N,K,ep,res); break;
        case 2: k_gemm_bf<2><<<g,256>>>(A,Bw,Cm,M,N,K,ep,res); break;
        case 3: k_gemm_bf<3><<<g,256>>>(A,Bw,Cm,M,N,K,ep,res); break;
        case 4: k_gemm_bf<4><<<g,256>>>(A,Bw,Cm,M,N,K,ep,res); break;
    }
}

extern "C" void kernel_launch(void* const* d_in, const int* in_sizes, int n_in,
                              void* d_out, int out_size)
{
    const float* fused        = (const float*)d_in[0];
    const float* depth        = (const float*)d_in[1];
    const float* pg_dw_w      = (const float*)d_in[2];
    const float* pg_bn1       = (const float*)d_in[3];
    const float* pg_pw_w      = (const float*)d_in[4];
    const float* pg_bn2       = (const float*)d_in[5];
    const float* prompt_embed = (const float*)d_in[6];
    const float* pg_ln        = (const float*)d_in[7];
    const float* gp_dw_w      = (const float*)d_in[8];
    const float* gp_bn        = (const float*)d_in[9];
    const float* gp_pw_w      = (const float*)d_in[10];
    const float* gp_pw_b      = (const float*)d_in[11];
    const float* gp_weight    = (const float*)d_in[12];
    const float* ln1          = (const float*)d_in[13];
    const float* wq           = (const float*)d_in[14];
    const float* wk           = (const float*)d_in[15];
    const float* wv           = (const float*)d_in[16];
    const float* wo           = (const float*)d_in[17];
    const float* ln2          = (const float*)d_in[18];
    const float* mlp_w1       = (const float*)d_in[19];
    const float* mlp_b1       = (const float*)d_in[20];
    const float* mlp_w2       = (const float*)d_in[21];
    const float* mlp_b2       = (const float*)d_in[22];
    const float* op_dw_w      = (const float*)d_in[23];
    const float* op_bn1       = (const float*)d_in[24];
    const float* op_pw_w      = (const float*)d_in[25];
    const float* op_bn2       = (const float*)d_in[26];

    float *dw1,*dsf,*pp1t,*pp2t,*ds,*prm,*jdb,*jt,*xb,*wqkv,*qkv,*aob,*hb,*enh,*o1c,*o1t,*o2t;
    cudaGetSymbolAddress((void**)&dw1,  g_dw1);
    cudaGetSymbolAddress((void**)&dsf,  g_dsf);
    cudaGetSymbolAddress((void**)&pp1t, g_pp1t);
    cudaGetSymbolAddress((void**)&pp2t, g_pp2t);
    cudaGetSymbolAddress((void**)&ds,   g_ds);
    cudaGetSymbolAddress((void**)&prm,  g_prompt);
    cudaGetSymbolAddress((void**)&jdb,  g_jd);
    cudaGetSymbolAddress((void**)&jt,   g_jt);
    cudaGetSymbolAddress((void**)&xb,   g_x);
    cudaGetSymbolAddress((void**)&wqkv, g_wqkv);
    cudaGetSymbolAddress((void**)&qkv,  g_qkv);
    cudaGetSymbolAddress((void**)&aob,  g_ao);
    cudaGetSymbolAddress((void**)&hb,   g_h);
    cudaGetSymbolAddress((void**)&enh,  g_enh);
    cudaGetSymbolAddress((void**)&o1c,  g_o1c);
    cudaGetSymbolAddress((void**)&o1t,  g_o1t);
    cudaGetSymbolAddress((void**)&o2t,  g_o2t);

    cudaFuncSetAttribute(k_attn, cudaFuncAttributeMaxDynamicSharedMemorySize, ATTN_SMEM);

    dim3 tgrid(CHW/32, CC/32, CB), tblk(32, 8);

    // concat qkv weights (device-to-device, capturable)
    cudaMemcpyAsync(wqkv,           wq, CC*CC*sizeof(float), cudaMemcpyDeviceToDevice);
    cudaMemcpyAsync(wqkv +   CC*CC, wk, CC*CC*sizeof(float), cudaMemcpyDeviceToDevice);
    cudaMemcpyAsync(wqkv + 2*CC*CC, wv, CC*CC*sizeof(float), cudaMemcpyDeviceToDevice);

    // --- DepthPromptGenerator + GeometryPriorGenerator shared dwconv ---
    k_dwconv_dual<<<(CB*CC*CHW)/256, 256>>>(depth, pg_dw_w, pg_bn1, dw1, gp_dw_w, gp_bn, dsf);
    k_cp_to_tok<<<tgrid, tblk>>>(dw1, pp1t, CHW, 0);
    launch_gemm(1, pp1t, pg_pw_w, pp2t, CB*CHW, CC, CC, pg_bn2, nullptr);   // bn2 + gelu
    k_gp_pw<<<(CB*CHW)/32, 256>>>(dsf, gp_pw_w, gp_pw_b, ds);
    k_prompt<<<CB*NPR, 256>>>(pp2t, prompt_embed, pg_ln, prm);
    k_jd<<<(CB*CN + 255)/256, 256>>>(ds, jdb);

    // --- assemble joint tokens ---
    k_copy_prompt<<<(CB*NPR*CC)/256, 256>>>(prm, jt);
    k_cp_to_tok<<<tgrid, tblk>>>(fused, jt, CN, NPR);

    // --- attention block ---
    k_ln<<<CB*CN, 256>>>(jt, ln1, xb);
    launch_gemm(0, xb, wqkv, qkv, CB*CN, QKV, CC, nullptr, nullptr);        // fused QKV
    k_attn<<<dim3(9, CNH, CB), 256, ATTN_SMEM>>>(qkv, jdb, gp_weight, aob);
    launch_gemm(4, aob, wo, jt, CB*CN, CC, CC, nullptr, jt);                // jt += ao@wo^T

    // --- MLP ---
    k_ln<<<CB*CN, 256>>>(jt, ln2, xb);
    launch_gemm(2, xb, mlp_w1, hb, CB*CN, HID, CC, mlp_b1, nullptr);        // bias + gelu
    launch_gemm(3, hb, mlp_w2, jt, CB*CN, CC, HID, mlp_b2, jt);             // bias + residual

    // --- out_proj ---
    k_tok_to_cp<<<tgrid, tblk>>>(jt, enh, CN, NPR);
    k_dwconv_dual<<<(CB*CC*CHW)/256, 256>>>(enh, op_dw_w, op_bn1, o1c, nullptr, nullptr, nullptr);
    k_cp_to_tok<<<tgrid, tblk>>>(o1c, o1t, CHW, 0);
    launch_gemm(0, o1t, op_pw_w, o2t, CB*CHW, CC, CC, nullptr, nullptr);
    k_final<<<tgrid, tblk>>>(fused, o2t, op_bn2, (float*)d_out);
}

// round 7
// speedup vs baseline: 1.5912x; 1.1664x over previous
#include <cuda_runtime.h>
#include <cuda_bf16.h>
#include <math.h>

// ---------------- problem constants ----------------
constexpr int CB  = 4;      // batch
constexpr int CC  = 512;    // channels
constexpr int CHH = 32;     // H
constexpr int CWW = 32;     // W
constexpr int CHW = 1024;   // H*W
constexpr int CNH = 8;      // heads
constexpr int NPR = 8;      // prompt tokens
constexpr int CN  = 1032;   // total tokens
constexpr int HID = 1024;   // mlp hidden
constexpr int QKV = 3*CC;   // fused qkv row stride
constexpr float EPS = 1e-5f;

// ---------------- scratch (static device memory; no allocations) ----------------
__device__ __align__(16) float g_dw1 [CB*CC*CHW];
__device__ __align__(16) float g_dsf [CB*CC*CHW];
__device__ __align__(16) float g_pp2t[CB*CHW*CC];
__device__ __align__(16) float g_ds  [CB*CHW];
__device__ __align__(16) float g_prompt[CB*NPR*CC];
__device__ __align__(16) float g_jd  [CB*CN];
__device__ __align__(16) float g_jt  [CB*CN*CC];
__device__ __align__(16) float g_enh [CB*CC*CHW];
__device__ __align__(16) float g_o1c [CB*CC*CHW];
__device__ __align__(16) float g_o2t [CB*CHW*CC];
// bf16 activations (GEMM operands)
__device__ __align__(16) __nv_bfloat16 g_pp1t_bf[CB*CHW*CC];
__device__ __align__(16) __nv_bfloat16 g_x_bf  [CB*CN*CC];
__device__ __align__(16) __nv_bfloat16 g_qkv_bf[CB*CN*QKV];
__device__ __align__(16) __nv_bfloat16 g_ao_bf [CB*CN*CC];
__device__ __align__(16) __nv_bfloat16 g_h_bf  [CB*CN*HID];
__device__ __align__(16) __nv_bfloat16 g_o1t_bf[CB*CHW*CC];
// bf16 packed weights
__device__ __align__(16) __nv_bfloat16 g_wpg [CC*CC];
__device__ __align__(16) __nv_bfloat16 g_wqkv[QKV*CC];
__device__ __align__(16) __nv_bfloat16 g_wo  [CC*CC];
__device__ __align__(16) __nv_bfloat16 g_w1  [HID*CC];
__device__ __align__(16) __nv_bfloat16 g_w2  [CC*HID];
__device__ __align__(16) __nv_bfloat16 g_wop [CC*CC];

__device__ __forceinline__ float gelu_f(float x){
    return 0.5f * x * (1.0f + erff(x * 0.70710678118654752f));
}
__device__ __forceinline__ unsigned pack_bf(float lo, float hi){
    unsigned r;
    asm("cvt.rn.bf16x2.f32 %0, %1, %2;" : "=r"(r) : "f"(hi), "f"(lo));
    return r;
}
__device__ __forceinline__ void mma_bf16(float& d0, float& d1, float& d2, float& d3,
                                         unsigned a0, unsigned a1, unsigned a2, unsigned a3,
                                         unsigned b0, unsigned b1)
{
    asm volatile("mma.sync.aligned.m16n8k16.row.col.f32.bf16.bf16.f32 "
                 "{%0,%1,%2,%3}, {%4,%5,%6,%7}, {%8,%9}, {%0,%1,%2,%3};"
                 : "+f"(d0), "+f"(d1), "+f"(d2), "+f"(d3)
                 : "r"(a0), "r"(a1), "r"(a2), "r"(a3), "r"(b0), "r"(b1));
}
__device__ __forceinline__ unsigned su32(const void* p){
    return (unsigned)__cvta_generic_to_shared(p);
}
__device__ __forceinline__ void ldsm4(unsigned& r0, unsigned& r1, unsigned& r2, unsigned& r3,
                                      unsigned addr){
    asm volatile("ldmatrix.sync.aligned.m8n8.x4.shared.b16 {%0,%1,%2,%3}, [%4];"
                 : "=r"(r0), "=r"(r1), "=r"(r2), "=r"(r3) : "r"(addr));
}
__device__ __forceinline__ void cp16(unsigned dst, const void* src, bool v){
    int sz = v ? 16 : 0;
    asm volatile("cp.async.cg.shared.global [%0], [%1], 16, %2;" :: "r"(dst), "l"(src), "r"(sz));
}
__device__ __forceinline__ void cp_commit(){ asm volatile("cp.async.commit_group;"); }
template<int N>
__device__ __forceinline__ void cp_wait(){ asm volatile("cp.async.wait_group %0;" :: "n"(N)); }

// ---------------- weight pack fp32 -> bf16 ----------------
__global__ void k_pack(const float* __restrict__ s, __nv_bfloat16* __restrict__ d, int n4)
{
    int i = blockIdx.x * 256 + threadIdx.x;
    if (i >= n4) return;
    float4 v = *(const float4*)(s + i*4);
    *(uint2*)(d + i*4) = make_uint2(pack_bf(v.x, v.y), pack_bf(v.z, v.w));
}

// ---------------- depthwise 3x3 conv + BN + GELU (optionally two branches) ----------------
__global__ void k_dwconv_dual(const float* __restrict__ in,
                              const float* __restrict__ w1, const float* __restrict__ bn1,
                              float* __restrict__ out1,
                              const float* __restrict__ w2, const float* __restrict__ bn2,
                              float* __restrict__ out2)
{
    int idx = blockIdx.x * 256 + threadIdx.x;
    if (idx >= CB*CC*CHW) return;
    int p = idx & (CHW-1);
    int c = (idx >> 10) & (CC-1);
    int y = p >> 5, x = p & 31;
    const float* base = in + (size_t)(idx - p);
    float v[9];
#pragma unroll
    for (int ky = 0; ky < 3; ky++)
#pragma unroll
        for (int kx = 0; kx < 3; kx++){
            int yy = y + ky - 1, xx = x + kx - 1;
            v[ky*3+kx] = (yy >= 0 && yy < CHH && xx >= 0 && xx < CWW) ? base[yy*CWW + xx] : 0.f;
        }
    {
        float a = 0.f;
#pragma unroll
        for (int k = 0; k < 9; k++) a += w1[c*9+k] * v[k];
        float s = bn1[c] * rsqrtf(bn1[3*CC+c] + EPS);
        a = a * s + bn1[CC+c] - bn1[2*CC+c] * s;
        out1[idx] = gelu_f(a);
    }
    if (out2){
        float a = 0.f;
#pragma unroll
        for (int k = 0; k < 9; k++) a += w2[c*9+k] * v[k];
        float s = bn2[c] * rsqrtf(bn2[3*CC+c] + EPS);
        a = a * s + bn2[CC+c] - bn2[2*CC+c] * s;
        out2[idx] = gelu_f(a);
    }
}

// ---------------- transposes ----------------
template<typename T>
__global__ void k_cp_to_tok(const float* __restrict__ in, T* __restrict__ out,
                            int tokTotal, int tokOff)
{
    __shared__ float tile[32][33];
    int b = blockIdx.z;
    int p0 = blockIdx.x * 32, c0 = blockIdx.y * 32;
    int tx = threadIdx.x, ty = threadIdx.y;
#pragma unroll
    for (int i = 0; i < 4; i++){
        int c = c0 + ty + i*8;
        tile[ty + i*8][tx] = in[((size_t)b*CC + c)*CHW + p0 + tx];
    }
    __syncthreads();
#pragma unroll
    for (int i = 0; i < 4; i++){
        int p = p0 + ty + i*8;
        out[((size_t)b*tokTotal + tokOff + p)*CC + c0 + tx] = (T)tile[tx][ty + i*8];
    }
}

__global__ void k_tok_to_cp(const float* __restrict__ in, float* __restrict__ out,
                            int tokTotal, int tokOff)
{
    __shared__ float tile[32][33];
    int b = blockIdx.z;
    int p0 = blockIdx.x * 32, c0 = blockIdx.y * 32;
    int tx = threadIdx.x, ty = threadIdx.y;
#pragma unroll
    for (int i = 0; i < 4; i++){
        int p = p0 + ty + i*8;
        tile[ty + i*8][tx] = in[((size_t)b*tokTotal + tokOff + p)*CC + c0 + tx];
    }
    __syncthreads();
#pragma unroll
    for (int i = 0; i < 4; i++){
        int c = c0 + ty + i*8;
        out[((size_t)b*CC + c)*CHW + p0 + tx] = tile[tx][ty + i*8];
    }
}

// ---------------- tensor-core NT GEMM: bf16 in, cp.async pipeline, ldmatrix ----------------
// C[m,n] = sum_k A[m,k]*B[n,k]  (A,B bf16 row-major). EPI: 0 plain, 1 bn+gelu, 2 bias+gelu,
// 3 bias+res, 4 res.  OBF: output bf16 (1) or fp32 (0).
constexpr int RSU   = 20;          // row stride in uints (16 data + 4 pad) -> conflict-free LDSM
constexpr int STG_U = 128*RSU;     // uints per matrix per stage
constexpr int NSTG  = 3;
constexpr int GEMM_SMEM = NSTG*STG_U*2*4;  // 61440 B

template<int EPI, int OBF>
__global__ void __launch_bounds__(256) k_gemm_bf(const __nv_bfloat16* __restrict__ A,
                                                 const __nv_bfloat16* __restrict__ Bw,
                                                 void* __restrict__ Cout,
                                                 int M, int N, int K,
                                                 const float* __restrict__ ep,
                                                 const float* __restrict__ res)
{
    extern __shared__ unsigned gsm[];
    unsigned* As = gsm;
    unsigned* Bs = gsm + NSTG*STG_U;
    unsigned as_u = su32(As), bs_u = su32(Bs);

    int tid  = threadIdx.x;
    int lane = tid & 31;
    int w    = tid >> 5;
    int wm   = w >> 1;
    int wn   = w & 1;
    int m0 = blockIdx.y * 128, n0 = blockIdx.x * 128;

    // cp.async mapping: 512 chunks of 16B per matrix per stage, 2 per thread
    int r0 = tid >> 2, c0 = (tid & 3);              // chunk row/col16
    const char* Ap0 = (const char*)(A + (size_t)(m0 + r0)*K + c0*8);
    const char* Ap1 = (const char*)(A + (size_t)(m0 + r0 + 64)*K + c0*8);
    const char* Bp0 = (const char*)(Bw + (size_t)(n0 + r0)*K + c0*8);
    const char* Bp1 = (const char*)(Bw + (size_t)(n0 + r0 + 64)*K + c0*8);
    bool av0 = (m0 + r0) < M, av1 = (m0 + r0 + 64) < M;
    unsigned ad0 = as_u + ((r0*RSU + c0*4) << 2);
    unsigned ad1 = as_u + (((r0+64)*RSU + c0*4) << 2);
    unsigned bd0 = bs_u + ((r0*RSU + c0*4) << 2);
    unsigned bd1 = bs_u + (((r0+64)*RSU + c0*4) << 2);

    float acc[2][8][4];
#pragma unroll
    for (int mf = 0; mf < 2; mf++)
#pragma unroll
        for (int nf = 0; nf < 8; nf++)
#pragma unroll
            for (int r = 0; r < 4; r++) acc[mf][nf][r] = 0.f;

    int NK = K >> 5;

    // prologue: stages 0..NSTG-2
#pragma unroll
    for (int st = 0; st < NSTG-1; st++){
        unsigned so = (st*STG_U) << 2;
        size_t go = (size_t)(st*32) * 2;  // bytes (32 bf16)
        cp16(ad0 + so, Ap0 + go, av0);
        cp16(ad1 + so, Ap1 + go, av1);
        cp16(bd0 + so, Bp0 + go, true);
        cp16(bd1 + so, Bp1 + go, true);
        cp_commit();
    }

    // fragment addresses (byte), stage 0
    int l7 = lane & 7;
    unsigned a_base[2], b_base[4];
    {
        int acol = ((lane >> 4) & 1) * 4;
        int ar = wm*32 + l7 + ((lane >> 3) & 1) * 8;
        a_base[0] = as_u + ((ar*RSU + acol) << 2);
        a_base[1] = as_u + (((ar+16)*RSU + acol) << 2);
        int bcol = ((lane >> 3) & 1) * 4;
        int brr  = wn*64 + l7 + (lane >> 4) * 8;
#pragma unroll
        for (int nf2 = 0; nf2 < 4; nf2++)
            b_base[nf2] = bs_u + (((brr + nf2*16)*RSU + bcol) << 2);
    }

    for (int kt = 0; kt < NK; kt++){
        cp_wait<NSTG-2>();
        __syncthreads();

        // issue loads for stage kt+NSTG-1
        int nk = kt + NSTG - 1;
        if (nk < NK){
            unsigned so = ((nk % NSTG)*STG_U) << 2;
            size_t go = (size_t)(nk*32) * 2;
            cp16(ad0 + so, Ap0 + go, av0);
            cp16(ad1 + so, Ap1 + go, av1);
            cp16(bd0 + so, Bp0 + go, true);
            cp16(bd1 + so, Bp1 + go, true);
        }
        cp_commit();

        unsigned soff = ((unsigned)(kt % NSTG) * STG_U) << 2;
#pragma unroll
        for (int kf = 0; kf < 2; kf++){
            unsigned ko = soff + kf*32;
            unsigned a[2][4];
            ldsm4(a[0][0], a[0][1], a[0][2], a[0][3], a_base[0] + ko);
            ldsm4(a[1][0], a[1][1], a[1][2], a[1][3], a_base[1] + ko);
#pragma unroll
            for (int nf2 = 0; nf2 < 4; nf2++){
                unsigned b0, b1, b2, b3;
                ldsm4(b0, b1, b2, b3, b_base[nf2] + ko);
#pragma unroll
                for (int mf = 0; mf < 2; mf++){
                    mma_bf16(acc[mf][nf2*2  ][0], acc[mf][nf2*2  ][1], acc[mf][nf2*2  ][2], acc[mf][nf2*2  ][3],
                             a[mf][0], a[mf][1], a[mf][2], a[mf][3], b0, b1);
                    mma_bf16(acc[mf][nf2*2+1][0], acc[mf][nf2*2+1][1], acc[mf][nf2*2+1][2], acc[mf][nf2*2+1][3],
                             a[mf][0], a[mf][1], a[mf][2], a[mf][3], b2, b3);
                }
            }
        }
        __syncthreads();
    }

    // epilogue
#pragma unroll
    for (int mf = 0; mf < 2; mf++){
#pragma unroll
        for (int ri = 0; ri < 2; ri++){
            int row = m0 + wm*32 + mf*16 + (lane >> 2) + ri*8;
            if (row >= M) continue;
            size_t base = (size_t)row * N;
#pragma unroll
            for (int nf = 0; nf < 8; nf++){
                int col = n0 + wn*64 + nf*8 + 2*(lane & 3);
                float v0 = acc[mf][nf][ri*2 + 0];
                float v1 = acc[mf][nf][ri*2 + 1];
                if (EPI == 1){
                    float s0 = ep[col]   * rsqrtf(ep[3*N+col]   + EPS);
                    float s1 = ep[col+1] * rsqrtf(ep[3*N+col+1] + EPS);
                    v0 = gelu_f(v0 * s0 + ep[N+col]   - ep[2*N+col]   * s0);
                    v1 = gelu_f(v1 * s1 + ep[N+col+1] - ep[2*N+col+1] * s1);
                } else if (EPI == 2){
                    v0 = gelu_f(v0 + ep[col]);
                    v1 = gelu_f(v1 + ep[col+1]);
                } else if (EPI == 3){
                    float2 rr2 = *(const float2*)(res + base + col);
                    v0 = rr2.x + v0 + ep[col];
                    v1 = rr2.y + v1 + ep[col+1];
                } else if (EPI == 4){
                    float2 rr2 = *(const float2*)(res + base + col);
                    v0 = rr2.x + v0;
                    v1 = rr2.y + v1;
                }
                if (OBF){
                    ((unsigned*)Cout)[(base + col) >> 1] = pack_bf(v0, v1);
                } else {
                    *(float2*)((float*)Cout + base + col) = make_float2(v0, v1);
                }
            }
        }
    }
}

// ---------------- geometry prior: 512->1 projection ----------------
__global__ void k_gp_pw(const float* __restrict__ dsf, const float* __restrict__ w,
                        const float* __restrict__ bias, float* __restrict__ ds)
{
    __shared__ float red[8][33];
    int px = threadIdx.x & 31;
    int cz = threadIdx.x >> 5;
    int p0 = blockIdx.x * 32;
    int b  = p0 >> 10;
    int p  = (p0 & (CHW-1)) + px;
    float acc = 0.f;
#pragma unroll
    for (int i = 0; i < 64; i++){
        int c = cz*64 + i;
        acc += w[c] * dsf[((size_t)b*CC + c)*CHW + p];
    }
    red[cz][px] = acc;
    __syncthreads();
    if (cz == 0){
        float s = 0.f;
#pragma unroll
        for (int z = 0; z < 8; z++) s += red[z][px];
        ds[p0 + px] = s + bias[0];
    }
}

// ---------------- prompt: pool + embed + LN ----------------
__global__ void k_prompt(const float* __restrict__ pp2t, const float* __restrict__ pe,
                         const float* __restrict__ lnp, float* __restrict__ out)
{
    int b = blockIdx.x >> 3, pr = blockIdx.x & 7;
    int iy = pr >> 2, ix = pr & 3;
    int t = threadIdx.x;
    float a0 = 0.f, a1 = 0.f;
    for (int py = 0; py < 16; py++)
        for (int px = 0; px < 8; px++){
            int p = (iy*16 + py)*CWW + ix*8 + px;
            const float* base = pp2t + ((size_t)b*CHW + p)*CC;
            a0 += base[t];
            a1 += base[t + 256];
        }
    a0 = a0 * (1.f/128.f) + pe[pr*CC + t];
    a1 = a1 * (1.f/128.f) + pe[pr*CC + t + 256];
    __shared__ float rs[256], rq[256];
    rs[t] = a0 + a1; rq[t] = a0*a0 + a1*a1;
    __syncthreads();
    for (int s = 128; s > 0; s >>= 1){
        if (t < s){ rs[t] += rs[t+s]; rq[t] += rq[t+s]; }
        __syncthreads();
    }
    float mean = rs[0] * (1.f/512.f);
    float var  = rq[0] * (1.f/512.f) - mean*mean;
    float inv  = rsqrtf(var + EPS);
    size_t o = ((size_t)b*NPR + pr) * CC;
    out[o + t]       = (a0 - mean) * inv * lnp[t]       + lnp[CC + t];
    out[o + t + 256] = (a1 - mean) * inv * lnp[t + 256] + lnp[CC + t + 256];
}

// ---------------- joint depth scalar per token ----------------
__global__ void k_jd(const float* __restrict__ ds, float* __restrict__ jd)
{
    int t = blockIdx.x * 256 + threadIdx.x;
    if (t >= CB*CN) return;
    int b = t / CN, n = t % CN;
    if (n >= NPR){
        jd[t] = ds[b*CHW + (n - NPR)];
    } else {
        int iy = n >> 2, ix = n & 3;
        float acc = 0.f;
        for (int py = 0; py < 16; py++)
            for (int px = 0; px < 8; px++)
                acc += ds[b*CHW + (iy*16 + py)*CWW + ix*8 + px];
        jd[t] = acc * (1.f/128.f);
    }
}

// ---------------- copy prompt tokens into jt ----------------
__global__ void k_copy_prompt(const float* __restrict__ pr, float* __restrict__ jt)
{
    int idx = blockIdx.x * 256 + threadIdx.x;
    if (idx >= CB*NPR*CC) return;
    int b = idx / (NPR*CC), r = idx % (NPR*CC);
    jt[(size_t)b*CN*CC + r] = pr[(size_t)b*NPR*CC + r];
}

// ---------------- layernorm over C per token (fp32 in, bf16 out) ----------------
__global__ void k_ln(const float* __restrict__ in, const float* __restrict__ p,
                     __nv_bfloat16* __restrict__ out)
{
    int tok = blockIdx.x;
    const float* row = in + (size_t)tok * CC;
    int t = threadIdx.x;
    float v0 = row[t], v1 = row[t + 256];
    __shared__ float rs[256], rq[256];
    rs[t] = v0 + v1; rq[t] = v0*v0 + v1*v1;
    __syncthreads();
    for (int s = 128; s > 0; s >>= 1){
        if (t < s){ rs[t] += rs[t+s]; rq[t] += rq[t+s]; }
        __syncthreads();
    }
    float mean = rs[0] * (1.f/512.f);
    float var  = rq[0] * (1.f/512.f) - mean*mean;
    float inv  = rsqrtf(var + EPS);
    size_t o = (size_t)tok * CC;
    out[o + t]       = __float2bfloat16((v0 - mean) * inv * p[t]       + p[CC + t]);
    out[o + t + 256] = __float2bfloat16((v1 - mean) * inv * p[t + 256] + p[CC + t + 256]);
}

// ---------------- attention: flash-style, bf16 mma, analytic bias ----------------
__device__ __forceinline__ void tok_coord(int n, float& cy, float& cx){
    if (n < NPR){ cy = (float)(n >> 2); cx = (float)(n & 3) * (1.f/3.f); }
    else { int m = n - NPR; cy = (float)(m >> 5) * (1.f/31.f); cx = (float)(m & 31) * (1.f/31.f); }
}

constexpr int AST = 36;                      // uint stride for 64-bf16 rows
constexpr int QS_OFF = 0;                    // 128 rows
constexpr int KS_OFF = QS_OFF + 128*AST;     // 64 rows
constexpr int VS_OFF = KS_OFF + 64*AST;      // 64 rows (transposed: rows = d)
constexpr int PS_OFF = VS_OFF + 64*AST;      // 128 rows
constexpr int KD_OFF = PS_OFF + 128*AST;     // 64 floats
constexpr int ATTN_SMEM = (KD_OFF + 64) * 4; // bytes

__global__ void __launch_bounds__(256) k_attn(const __nv_bfloat16* __restrict__ qkv,
                                              const float* __restrict__ jd,
                                              const float* __restrict__ gw,
                                              __nv_bfloat16* __restrict__ ao)
{
    extern __shared__ unsigned smu[];
    unsigned* Qs = smu + QS_OFF;
    unsigned* Ks = smu + KS_OFF;
    unsigned* Vt = smu + VS_OFF;
    unsigned* Ps = smu + PS_OFF;
    float*  kdep = (float*)(smu + KD_OFF);
    __nv_bfloat16* Vt16 = (__nv_bfloat16*)Vt;

    int b = blockIdx.z, h = blockIdx.y, q0 = blockIdx.x * 128;
    int tid = threadIdx.x, lane = tid & 31, w = tid >> 5;
    int c = lane & 3, gr = lane >> 2;

    const float decay = logf(1.f - exp2f(-1.f - 0.5f * (float)h));
    const float w0 = gw[0] * decay, w1 = gw[1] * decay;

    // load Q tile (128 x 64 bf16): 1024 uint4 chunks, 4 per thread
#pragma unroll
    for (int j = 0; j < 4; j++){
        int i = tid + 256*j;
        int r = i >> 3, c4 = i & 7;
        int qn = q0 + r;
        uint4 v = (qn < CN) ? *(const uint4*)(qkv + ((size_t)b*CN + qn)*QKV + h*64 + c4*8)
                            : make_uint4(0,0,0,0);
        *(uint4*)&Qs[r*AST + c4*4] = v;
    }

    float qy[2], qx[2], qd[2];
#pragma unroll
    for (int i = 0; i < 2; i++){
        int qn = q0 + w*16 + gr + i*8;
        if (qn < CN){ tok_coord(qn, qy[i], qx[i]); qd[i] = jd[b*CN + qn]; }
        else { qy[i] = qx[i] = qd[i] = 0.f; }
    }

    float O[8][4];
#pragma unroll
    for (int nf = 0; nf < 8; nf++)
#pragma unroll
        for (int r = 0; r < 4; r++) O[nf][r] = 0.f;
    float mi[2] = {-1e30f, -1e30f}, li[2] = {0.f, 0.f};

    for (int kt = 0; kt < 17; kt++){
        int k0 = kt * 64;
        __syncthreads();
        // load K (rows = key) and V transposed (rows = d): 512 uint4 each, 2 per thread
#pragma unroll
        for (int j = 0; j < 2; j++){
            int i = tid + 256*j;
            int r = i >> 3, c4 = i & 7;
            int n = k0 + r;
            bool val = (n < CN);
            const __nv_bfloat16* rowp = qkv + ((size_t)b*CN + n)*QKV + h*64;
            uint4 kv = val ? *(const uint4*)(rowp + CC  + c4*8) : make_uint4(0,0,0,0);
            uint4 vv = val ? *(const uint4*)(rowp + 2*CC + c4*8) : make_uint4(0,0,0,0);
            *(uint4*)&Ks[r*AST + c4*4] = kv;
            const __nv_bfloat16* vp = (const __nv_bfloat16*)&vv;
#pragma unroll
            for (int d = 0; d < 8; d++)
                Vt16[(c4*8 + d)*(AST*2) + r] = vp[d];
        }
        if (tid < 64) kdep[tid] = (k0 + tid < CN) ? jd[b*CN + k0 + tid] : 0.f;
        __syncthreads();

        float S[8][4];
#pragma unroll
        for (int nf = 0; nf < 8; nf++)
#pragma unroll
            for (int r = 0; r < 4; r++) S[nf][r] = 0.f;
        int rbase = w*16 + gr;
#pragma unroll
        for (int kf = 0; kf < 4; kf++){
            int kc = kf*8 + c;
            unsigned a0 = Qs[(rbase    )*AST + kc    ];
            unsigned a1 = Qs[(rbase + 8)*AST + kc    ];
            unsigned a2 = Qs[(rbase    )*AST + kc + 4];
            unsigned a3 = Qs[(rbase + 8)*AST + kc + 4];
#pragma unroll
            for (int nf = 0; nf < 8; nf++){
                int nb = nf*8 + gr;
                unsigned b0 = Ks[nb*AST + kc];
                unsigned b1 = Ks[nb*AST + kc + 4];
                mma_bf16(S[nf][0], S[nf][1], S[nf][2], S[nf][3], a0, a1, a2, a3, b0, b1);
            }
        }

        bool kval[8][2];
#pragma unroll
        for (int nf = 0; nf < 8; nf++){
#pragma unroll
            for (int j = 0; j < 2; j++){
                int kl = nf*8 + c*2 + j;
                int kn = k0 + kl;
                kval[nf][j] = (kn < CN);
                float ky, kx;
                tok_coord(kn, ky, kx);
                float kd = kdep[kl];
#pragma unroll
                for (int i = 0; i < 2; i++){
                    float pos = fabsf(qy[i]-ky) + fabsf(qx[i]-kx);
                    float vv = S[nf][i*2+j]*0.125f + w0*pos + w1*fabsf(qd[i]-kd);
                    S[nf][i*2+j] = kval[nf][j] ? vv : -1e30f;
                }
            }
        }

        float alpha[2];
#pragma unroll
        for (int i = 0; i < 2; i++){
            float tm = -1e30f;
#pragma unroll
            for (int nf = 0; nf < 8; nf++){
                tm = fmaxf(tm, S[nf][i*2]);
                tm = fmaxf(tm, S[nf][i*2+1]);
            }
            tm = fmaxf(tm, __shfl_xor_sync(0xffffffffu, tm, 1));
            tm = fmaxf(tm, __shfl_xor_sync(0xffffffffu, tm, 2));
            float mn = fmaxf(mi[i], tm);
            alpha[i] = __expf(mi[i] - mn);
            float ssum = 0.f;
#pragma unroll
            for (int nf = 0; nf < 8; nf++){
#pragma unroll
                for (int j = 0; j < 2; j++){
                    float p = kval[nf][j] ? __expf(S[nf][i*2+j] - mn) : 0.f;
                    S[nf][i*2+j] = p;
                    ssum += p;
                }
            }
            ssum += __shfl_xor_sync(0xffffffffu, ssum, 1);
            ssum += __shfl_xor_sync(0xffffffffu, ssum, 2);
            li[i] = li[i]*alpha[i] + ssum;
            mi[i] = mn;
        }
#pragma unroll
        for (int nf = 0; nf < 8; nf++){
            O[nf][0] *= alpha[0]; O[nf][1] *= alpha[0];
            O[nf][2] *= alpha[1]; O[nf][3] *= alpha[1];
        }
#pragma unroll
        for (int nf = 0; nf < 8; nf++){
#pragma unroll
            for (int i = 0; i < 2; i++){
                int r = rbase + i*8;
                Ps[r*AST + nf*4 + c] = pack_bf(S[nf][i*2], S[nf][i*2+1]);
            }
        }
        __syncwarp();

#pragma unroll
        for (int kf = 0; kf < 4; kf++){
            int kc = kf*8 + c;
            unsigned a0 = Ps[(rbase    )*AST + kc    ];
            unsigned a1 = Ps[(rbase + 8)*AST + kc    ];
            unsigned a2 = Ps[(rbase    )*AST + kc + 4];
            unsigned a3 = Ps[(rbase + 8)*AST + kc + 4];
#pragma unroll
            for (int nf = 0; nf < 8; nf++){
                int d = nf*8 + gr;
                unsigned b0 = Vt[d*AST + kc];
                unsigned b1 = Vt[d*AST + kc + 4];
                mma_bf16(O[nf][0], O[nf][1], O[nf][2], O[nf][3], a0, a1, a2, a3, b0, b1);
            }
        }
    }

    // epilogue (bf16)
#pragma unroll
    for (int i = 0; i < 2; i++){
        int qn = q0 + w*16 + gr + i*8;
        if (qn >= CN) continue;
        float invl = 1.f / li[i];
        size_t base = ((size_t)b*CN + qn)*CC + h*64;
#pragma unroll
        for (int nf = 0; nf < 8; nf++){
            int cc2 = nf*8 + c*2;
            ((unsigned*)ao)[(base + cc2) >> 1] = pack_bf(O[nf][i*2]*invl, O[nf][i*2+1]*invl);
        }
    }
}

// ---------------- final: out = fused + BN(op_pw output), with transpose ----------------
__global__ void k_final(const float* __restrict__ fused, const float* __restrict__ o2t,
                        const float* __restrict__ bn, float* __restrict__ out)
{
    __shared__ float tile[32][33];
    int b = blockIdx.z;
    int p0 = blockIdx.x * 32, c0 = blockIdx.y * 32;
    int tx = threadIdx.x, ty = threadIdx.y;
#pragma unroll
    for (int i = 0; i < 4; i++){
        int p = p0 + ty + i*8;
        tile[ty + i*8][tx] = o2t[((size_t)b*CHW + p)*CC + c0 + tx];
    }
    __syncthreads();
#pragma unroll
    for (int i = 0; i < 4; i++){
        int c = c0 + ty + i*8;
        float s = bn[c] * rsqrtf(bn[3*CC+c] + EPS);
        float t = bn[CC+c] - bn[2*CC+c] * s;
        size_t idx = ((size_t)b*CC + c)*CHW + p0 + tx;
        out[idx] = fused[idx] + tile[tx][ty + i*8] * s + t;
    }
}

// ---------------- host ----------------
template<int EPI, int OBF>
static void gemm_go(const __nv_bfloat16* A, const __nv_bfloat16* Bw, void* Cm,
                    int M, int N, int K, const float* ep, const float* res)
{
    cudaFuncSetAttribute(k_gemm_bf<EPI,OBF>, cudaFuncAttributeMaxDynamicSharedMemorySize, GEMM_SMEM);
    dim3 g(N/128, (M + 127)/128);
    k_gemm_bf<EPI,OBF><<<g, 256, GEMM_SMEM>>>(A, Bw, Cm, M, N, K, ep, res);
}

static void pack_w(const float* s, __nv_bfloat16* d, int n)
{
    k_pack<<<(n/4 + 255)/256, 256>>>(s, d, n/4);
}

extern "C" void kernel_launch(void* const* d_in, const int* in_sizes, int n_in,
                              void* d_out, int out_size)
{
    const float* fused        = (const float*)d_in[0];
    const float* depth        = (const float*)d_in[1];
    const float* pg_dw_w      = (const float*)d_in[2];
    const float* pg_bn1       = (const float*)d_in[3];
    const float* pg_pw_w      = (const float*)d_in[4];
    const float* pg_bn2       = (const float*)d_in[5];
    const float* prompt_embed = (const float*)d_in[6];
    const float* pg_ln        = (const float*)d_in[7];
    const float* gp_dw_w      = (const float*)d_in[8];
    const float* gp_bn        = (const float*)d_in[9];
    const float* gp_pw_w      = (const float*)d_in[10];
    const float* gp_pw_b      = (const float*)d_in[11];
    const float* gp_weight    = (const float*)d_in[12];
    const float* ln1          = (const float*)d_in[13];
    const float* wq           = (const float*)d_in[14];
    const float* wk           = (const float*)d_in[15];
    const float* wv           = (const float*)d_in[16];
    const float* wo           = (const float*)d_in[17];
    const float* ln2          = (const float*)d_in[18];
    const float* mlp_w1       = (const float*)d_in[19];
    const float* mlp_b1       = (const float*)d_in[20];
    const float* mlp_w2       = (const float*)d_in[21];
    const float* mlp_b2       = (const float*)d_in[22];
    const float* op_dw_w      = (const float*)d_in[23];
    const float* op_bn1       = (const float*)d_in[24];
    const float* op_pw_w      = (const float*)d_in[25];
    const float* op_bn2       = (const float*)d_in[26];

    float *dw1,*dsf,*pp2t,*ds,*prm,*jdb,*jt,*enh,*o1c,*o2t;
    __nv_bfloat16 *pp1t,*xb,*qkv,*aob,*hb,*o1t,*wpg,*wqkvb,*wob,*w1b,*w2b,*wopb;
    cudaGetSymbolAddress((void**)&dw1,  g_dw1);
    cudaGetSymbolAddress((void**)&dsf,  g_dsf);
    cudaGetSymbolAddress((void**)&pp2t, g_pp2t);
    cudaGetSymbolAddress((void**)&ds,   g_ds);
    cudaGetSymbolAddress((void**)&prm,  g_prompt);
    cudaGetSymbolAddress((void**)&jdb,  g_jd);
    cudaGetSymbolAddress((void**)&jt,   g_jt);
    cudaGetSymbolAddress((void**)&enh,  g_enh);
    cudaGetSymbolAddress((void**)&o1c,  g_o1c);
    cudaGetSymbolAddress((void**)&o2t,  g_o2t);
    cudaGetSymbolAddress((void**)&pp1t, g_pp1t_bf);
    cudaGetSymbolAddress((void**)&xb,   g_x_bf);
    cudaGetSymbolAddress((void**)&qkv,  g_qkv_bf);
    cudaGetSymbolAddress((void**)&aob,  g_ao_bf);
    cudaGetSymbolAddress((void**)&hb,   g_h_bf);
    cudaGetSymbolAddress((void**)&o1t,  g_o1t_bf);
    cudaGetSymbolAddress((void**)&wpg,  g_wpg);
    cudaGetSymbolAddress((void**)&wqkvb,g_wqkv);
    cudaGetSymbolAddress((void**)&wob,  g_wo);
    cudaGetSymbolAddress((void**)&w1b,  g_w1);
    cudaGetSymbolAddress((void**)&w2b,  g_w2);
    cudaGetSymbolAddress((void**)&wopb, g_wop);

    cudaFuncSetAttribute(k_attn, cudaFuncAttributeMaxDynamicSharedMemorySize, ATTN_SMEM);

    dim3 tgrid(CHW/32, CC/32, CB), tblk(32, 8);

    // pack weights to bf16
    pack_w(pg_pw_w, wpg, CC*CC);
    pack_w(wq, wqkvb,          CC*CC);
    pack_w(wk, wqkvb + CC*CC,  CC*CC);
    pack_w(wv, wqkvb + 2*CC*CC,CC*CC);
    pack_w(wo, wob, CC*CC);
    pack_w(mlp_w1, w1b, HID*CC);
    pack_w(mlp_w2, w2b, CC*HID);
    pack_w(op_pw_w, wopb, CC*CC);

    // --- DepthPromptGenerator + GeometryPriorGenerator shared dwconv ---
    k_dwconv_dual<<<(CB*CC*CHW)/256, 256>>>(depth, pg_dw_w, pg_bn1, dw1, gp_dw_w, gp_bn, dsf);
    k_cp_to_tok<__nv_bfloat16><<<tgrid, tblk>>>(dw1, pp1t, CHW, 0);
    gemm_go<1,0>(pp1t, wpg, pp2t, CB*CHW, CC, CC, pg_bn2, nullptr);   // bn2 + gelu
    k_gp_pw<<<(CB*CHW)/32, 256>>>(dsf, gp_pw_w, gp_pw_b, ds);
    k_prompt<<<CB*NPR, 256>>>(pp2t, prompt_embed, pg_ln, prm);
    k_jd<<<(CB*CN + 255)/256, 256>>>(ds, jdb);

    // --- assemble joint tokens ---
    k_copy_prompt<<<(CB*NPR*CC)/256, 256>>>(prm, jt);
    k_cp_to_tok<float><<<tgrid, tblk>>>(fused, jt, CN, NPR);

    // --- attention block ---
    k_ln<<<CB*CN, 256>>>(jt, ln1, xb);
    gemm_go<0,1>(xb, wqkvb, qkv, CB*CN, QKV, CC, nullptr, nullptr);   // fused QKV -> bf16
    k_attn<<<dim3(9, CNH, CB), 256, ATTN_SMEM>>>(qkv, jdb, gp_weight, aob);
    gemm_go<4,0>(aob, wob, jt, CB*CN, CC, CC, nullptr, jt);           // jt += ao@wo^T

    // --- MLP ---
    k_ln<<<CB*CN, 256>>>(jt, ln2, xb);
    gemm_go<2,1>(xb, w1b, hb, CB*CN, HID, CC, mlp_b1, nullptr);       // bias + gelu -> bf16
    gemm_go<3,0>(hb, w2b, jt, CB*CN, CC, HID, mlp_b2, jt);            // bias + residual

    // --- out_proj ---
    k_tok_to_cp<<<tgrid, tblk>>>(jt, enh, CN, NPR);
    k_dwconv_dual<<<(CB*CC*CHW)/256, 256>>>(enh, op_dw_w, op_bn1, o1c, nullptr, nullptr, nullptr);
    k_cp_to_tok<__nv_bfloat16><<<tgrid, tblk>>>(o1c, o1t, CHW, 0);
    gemm_go<0,0>(o1t, wopb, o2t, CB*CHW, CC, CC, nullptr, nullptr);
    k_final<<<tgrid, tblk>>>(fused, o2t, op_bn2, (float*)d_out);
}

// round 8
// speedup vs baseline: 1.7976x; 1.1297x over previous
#include <cuda_runtime.h>
#include <cuda_bf16.h>
#include <math.h>

// ---------------- problem constants ----------------
constexpr int CB  = 4;      // batch
constexpr int CC  = 512;    // channels
constexpr int CHH = 32;     // H
constexpr int CWW = 32;     // W
constexpr int CHW = 1024;   // H*W
constexpr int CNH = 8;      // heads
constexpr int NPR = 8;      // prompt tokens
constexpr int CN  = 1032;   // total tokens
constexpr int HID = 1024;   // mlp hidden
constexpr int QKV = 3*CC;   // fused qkv row stride
constexpr float EPS = 1e-5f;

// weight arena offsets (floats/bf16 elements)
constexpr int OPG  = 0;
constexpr int OQKV = 262144;           // wq,wk,wv consecutive
constexpr int OWO  = OQKV + 3*262144;  // 1048576
constexpr int OW1  = OWO + 262144;     // 1310720
constexpr int OW2  = OW1 + 524288;     // 1835008
constexpr int OWOP = OW2 + 524288;     // 2359296
constexpr int WALL = OWOP + 262144;    // 2621440

// ---------------- scratch (static device memory; no allocations) ----------------
__device__ __align__(16) float g_dsf [CB*CC*CHW];
__device__ __align__(16) float g_pp2t[CB*CHW*CC];
__device__ __align__(16) float g_ds  [CB*CHW];
__device__ __align__(16) float g_jd  [CB*CN];
__device__ __align__(16) float g_jt  [CB*CN*CC];
__device__ __align__(16) float g_enh [CB*CC*CHW];
__device__ __align__(16) float g_o2t [CB*CHW*CC];
__device__ __align__(16) __nv_bfloat16 g_pp1t_bf[CB*CHW*CC];
__device__ __align__(16) __nv_bfloat16 g_x_bf  [CB*CN*CC];
__device__ __align__(16) __nv_bfloat16 g_qkv_bf[CB*CN*QKV];
__device__ __align__(16) __nv_bfloat16 g_ao_bf [CB*CN*CC];
__device__ __align__(16) __nv_bfloat16 g_h_bf  [CB*CN*HID];
__device__ __align__(16) __nv_bfloat16 g_o1t_bf[CB*CHW*CC];
__device__ __align__(16) __nv_bfloat16 g_wall  [WALL];

__device__ __forceinline__ float gelu_f(float x){
    return 0.5f * x * (1.0f + erff(x * 0.70710678118654752f));
}
__device__ __forceinline__ unsigned pack_bf(float lo, float hi){
    unsigned r;
    asm("cvt.rn.bf16x2.f32 %0, %1, %2;" : "=r"(r) : "f"(hi), "f"(lo));
    return r;
}
__device__ __forceinline__ void mma_bf16(float& d0, float& d1, float& d2, float& d3,
                                         unsigned a0, unsigned a1, unsigned a2, unsigned a3,
                                         unsigned b0, unsigned b1)
{
    asm volatile("mma.sync.aligned.m16n8k16.row.col.f32.bf16.bf16.f32 "
                 "{%0,%1,%2,%3}, {%4,%5,%6,%7}, {%8,%9}, {%0,%1,%2,%3};"
                 : "+f"(d0), "+f"(d1), "+f"(d2), "+f"(d3)
                 : "r"(a0), "r"(a1), "r"(a2), "r"(a3), "r"(b0), "r"(b1));
}
__device__ __forceinline__ unsigned su32(const void* p){
    return (unsigned)__cvta_generic_to_shared(p);
}
__device__ __forceinline__ void ldsm4(unsigned& r0, unsigned& r1, unsigned& r2, unsigned& r3,
                                      unsigned addr){
    asm volatile("ldmatrix.sync.aligned.m8n8.x4.shared.b16 {%0,%1,%2,%3}, [%4];"
                 : "=r"(r0), "=r"(r1), "=r"(r2), "=r"(r3) : "r"(addr));
}
__device__ __forceinline__ void ldsm4t(unsigned& r0, unsigned& r1, unsigned& r2, unsigned& r3,
                                       unsigned addr){
    asm volatile("ldmatrix.sync.aligned.m8n8.x4.trans.shared.b16 {%0,%1,%2,%3}, [%4];"
                 : "=r"(r0), "=r"(r1), "=r"(r2), "=r"(r3) : "r"(addr));
}
__device__ __forceinline__ void cp16(unsigned dst, const void* src, bool v){
    int sz = v ? 16 : 0;
    asm volatile("cp.async.cg.shared.global [%0], [%1], 16, %2;" :: "r"(dst), "l"(src), "r"(sz));
}
__device__ __forceinline__ void cp_commit(){ asm volatile("cp.async.commit_group;"); }
template<int N>
__device__ __forceinline__ void cp_wait(){ asm volatile("cp.async.wait_group %0;" :: "n"(N)); }

// ---------------- single fused weight pack ----------------
__global__ void k_pack_all(const float* __restrict__ pg, const float* __restrict__ wq,
                           const float* __restrict__ wk, const float* __restrict__ wv,
                           const float* __restrict__ wo, const float* __restrict__ w1,
                           const float* __restrict__ w2, const float* __restrict__ wop,
                           __nv_bfloat16* __restrict__ d)
{
    int i = blockIdx.x * 256 + threadIdx.x;
    if (i >= WALL/4) return;
    int f = i * 4;
    const float* s; int base;
    if      (f < OQKV)              { s = pg;  base = OPG;  }
    else if (f < OQKV + 262144)     { s = wq;  base = OQKV; }
    else if (f < OQKV + 2*262144)   { s = wk;  base = OQKV + 262144; }
    else if (f < OWO)               { s = wv;  base = OQKV + 2*262144; }
    else if (f < OW1)               { s = wo;  base = OWO;  }
    else if (f < OW2)               { s = w1;  base = OW1;  }
    else if (f < OWOP)              { s = w2;  base = OW2;  }
    else                            { s = wop; base = OWOP; }
    float4 v = *(const float4*)(s + (f - base));
    *(uint2*)(d + f) = make_uint2(pack_bf(v.x, v.y), pack_bf(v.z, v.w));
}

// ---------------- fused depthwise 3x3 conv + BN + GELU + transpose-to-token (bf16) ----------
// out1t: [B][HW][C] bf16; optional out2c: [B][C][HW] fp32 (second branch)
template<int DUAL>
__global__ void k_dwconv_t(const float* __restrict__ in,
                           const float* __restrict__ w1, const float* __restrict__ bn1,
                           __nv_bfloat16* __restrict__ out1t,
                           const float* __restrict__ w2, const float* __restrict__ bn2,
                           float* __restrict__ out2c)
{
    __shared__ float tile[32][33];
    int b = blockIdx.z;
    int p0 = blockIdx.x * 32, c0 = blockIdx.y * 32;
    int tx = threadIdx.x, ty = threadIdx.y;
    int p = p0 + tx, y = p >> 5, x = p & 31;
#pragma unroll
    for (int i = 0; i < 4; i++){
        int c = c0 + ty + i*8;
        const float* base = in + (((size_t)b*CC + c) << 10);
        float v[9];
#pragma unroll
        for (int ky = 0; ky < 3; ky++)
#pragma unroll
            for (int kx = 0; kx < 3; kx++){
                int yy = y + ky - 1, xx = x + kx - 1;
                v[ky*3+kx] = (yy >= 0 && yy < CHH && xx >= 0 && xx < CWW) ? base[yy*CWW + xx] : 0.f;
            }
        float a1 = 0.f;
#pragma unroll
        for (int k = 0; k < 9; k++) a1 += w1[c*9+k] * v[k];
        float s1 = bn1[c] * rsqrtf(bn1[3*CC+c] + EPS);
        a1 = a1 * s1 + bn1[CC+c] - bn1[2*CC+c] * s1;
        tile[ty + i*8][tx] = gelu_f(a1);
        if (DUAL){
            float a2 = 0.f;
#pragma unroll
            for (int k = 0; k < 9; k++) a2 += w2[c*9+k] * v[k];
            float s2 = bn2[c] * rsqrtf(bn2[3*CC+c] + EPS);
            a2 = a2 * s2 + bn2[CC+c] - bn2[2*CC+c] * s2;
            out2c[(((size_t)b*CC + c) << 10) + p] = gelu_f(a2);
        }
    }
    __syncthreads();
#pragma unroll
    for (int i = 0; i < 4; i++){
        int pp_ = p0 + ty + i*8;
        out1t[((size_t)b*CHW + pp_)*CC + c0 + tx] = __float2bfloat16(tile[tx][ty + i*8]);
    }
}

// ---------------- transposes ----------------
__global__ void k_cp_to_tok_f(const float* __restrict__ in, float* __restrict__ out,
                              int tokTotal, int tokOff)
{
    __shared__ float tile[32][33];
    int b = blockIdx.z;
    int p0 = blockIdx.x * 32, c0 = blockIdx.y * 32;
    int tx = threadIdx.x, ty = threadIdx.y;
#pragma unroll
    for (int i = 0; i < 4; i++){
        int c = c0 + ty + i*8;
        tile[ty + i*8][tx] = in[((size_t)b*CC + c)*CHW + p0 + tx];
    }
    __syncthreads();
#pragma unroll
    for (int i = 0; i < 4; i++){
        int p = p0 + ty + i*8;
        out[((size_t)b*tokTotal + tokOff + p)*CC + c0 + tx] = tile[tx][ty + i*8];
    }
}

__global__ void k_tok_to_cp(const float* __restrict__ in, float* __restrict__ out,
                            int tokTotal, int tokOff)
{
    __shared__ float tile[32][33];
    int b = blockIdx.z;
    int p0 = blockIdx.x * 32, c0 = blockIdx.y * 32;
    int tx = threadIdx.x, ty = threadIdx.y;
#pragma unroll
    for (int i = 0; i < 4; i++){
        int p = p0 + ty + i*8;
        tile[ty + i*8][tx] = in[((size_t)b*tokTotal + tokOff + p)*CC + c0 + tx];
    }
    __syncthreads();
#pragma unroll
    for (int i = 0; i < 4; i++){
        int c = c0 + ty + i*8;
        out[((size_t)b*CC + c)*CHW + p0 + tx] = tile[tx][ty + i*8];
    }
}

// ---------------- tensor-core NT GEMM: bf16 in, cp.async pipeline, ldmatrix ----------------
constexpr int RSU   = 20;          // row stride in uints
constexpr int STG_U = 128*RSU;
constexpr int NSTG  = 3;
constexpr int GEMM_SMEM = NSTG*STG_U*2*4;

template<int EPI, int OBF>
__global__ void __launch_bounds__(256) k_gemm_bf(const __nv_bfloat16* __restrict__ A,
                                                 const __nv_bfloat16* __restrict__ Bw,
                                                 void* __restrict__ Cout,
                                                 int M, int N, int K,
                                                 const float* __restrict__ ep,
                                                 const float* __restrict__ res)
{
    extern __shared__ unsigned gsm[];
    unsigned* As = gsm;
    unsigned* Bs = gsm + NSTG*STG_U;
    unsigned as_u = su32(As), bs_u = su32(Bs);

    int tid  = threadIdx.x;
    int lane = tid & 31;
    int w    = tid >> 5;
    int wm   = w >> 1;
    int wn   = w & 1;
    int m0 = blockIdx.y * 128, n0 = blockIdx.x * 128;

    int r0 = tid >> 2, c0 = (tid & 3);
    const char* Ap0 = (const char*)(A + (size_t)(m0 + r0)*K + c0*8);
    const char* Ap1 = (const char*)(A + (size_t)(m0 + r0 + 64)*K + c0*8);
    const char* Bp0 = (const char*)(Bw + (size_t)(n0 + r0)*K + c0*8);
    const char* Bp1 = (const char*)(Bw + (size_t)(n0 + r0 + 64)*K + c0*8);
    bool av0 = (m0 + r0) < M, av1 = (m0 + r0 + 64) < M;
    unsigned ad0 = as_u + ((r0*RSU + c0*4) << 2);
    unsigned ad1 = as_u + (((r0+64)*RSU + c0*4) << 2);
    unsigned bd0 = bs_u + ((r0*RSU + c0*4) << 2);
    unsigned bd1 = bs_u + (((r0+64)*RSU + c0*4) << 2);

    float acc[2][8][4];
#pragma unroll
    for (int mf = 0; mf < 2; mf++)
#pragma unroll
        for (int nf = 0; nf < 8; nf++)
#pragma unroll
            for (int r = 0; r < 4; r++) acc[mf][nf][r] = 0.f;

    int NK = K >> 5;

#pragma unroll
    for (int st = 0; st < NSTG-1; st++){
        unsigned so = (st*STG_U) << 2;
        size_t go = (size_t)(st*32) * 2;
        cp16(ad0 + so, Ap0 + go, av0);
        cp16(ad1 + so, Ap1 + go, av1);
        cp16(bd0 + so, Bp0 + go, true);
        cp16(bd1 + so, Bp1 + go, true);
        cp_commit();
    }

    int l7 = lane & 7;
    unsigned a_base[2], b_base[4];
    {
        int acol = ((lane >> 4) & 1) * 4;
        int ar = wm*32 + l7 + ((lane >> 3) & 1) * 8;
        a_base[0] = as_u + ((ar*RSU + acol) << 2);
        a_base[1] = as_u + (((ar+16)*RSU + acol) << 2);
        int bcol = ((lane >> 3) & 1) * 4;
        int brr  = wn*64 + l7 + (lane >> 4) * 8;
#pragma unroll
        for (int nf2 = 0; nf2 < 4; nf2++)
            b_base[nf2] = bs_u + (((brr + nf2*16)*RSU + bcol) << 2);
    }

    for (int kt = 0; kt < NK; kt++){
        cp_wait<NSTG-2>();
        __syncthreads();

        int nk = kt + NSTG - 1;
        if (nk < NK){
            unsigned so = ((nk % NSTG)*STG_U) << 2;
            size_t go = (size_t)(nk*32) * 2;
            cp16(ad0 + so, Ap0 + go, av0);
            cp16(ad1 + so, Ap1 + go, av1);
            cp16(bd0 + so, Bp0 + go, true);
            cp16(bd1 + so, Bp1 + go, true);
        }
        cp_commit();

        unsigned soff = ((unsigned)(kt % NSTG) * STG_U) << 2;
#pragma unroll
        for (int kf = 0; kf < 2; kf++){
            unsigned ko = soff + kf*32;
            unsigned a[2][4];
            ldsm4(a[0][0], a[0][1], a[0][2], a[0][3], a_base[0] + ko);
            ldsm4(a[1][0], a[1][1], a[1][2], a[1][3], a_base[1] + ko);
#pragma unroll
            for (int nf2 = 0; nf2 < 4; nf2++){
                unsigned b0, b1, b2, b3;
                ldsm4(b0, b1, b2, b3, b_base[nf2] + ko);
#pragma unroll
                for (int mf = 0; mf < 2; mf++){
                    mma_bf16(acc[mf][nf2*2  ][0], acc[mf][nf2*2  ][1], acc[mf][nf2*2  ][2], acc[mf][nf2*2  ][3],
                             a[mf][0], a[mf][1], a[mf][2], a[mf][3], b0, b1);
                    mma_bf16(acc[mf][nf2*2+1][0], acc[mf][nf2*2+1][1], acc[mf][nf2*2+1][2], acc[mf][nf2*2+1][3],
                             a[mf][0], a[mf][1], a[mf][2], a[mf][3], b2, b3);
                }
            }
        }
        __syncthreads();
    }

#pragma unroll
    for (int mf = 0; mf < 2; mf++){
#pragma unroll
        for (int ri = 0; ri < 2; ri++){
            int row = m0 + wm*32 + mf*16 + (lane >> 2) + ri*8;
            if (row >= M) continue;
            size_t base = (size_t)row * N;
#pragma unroll
            for (int nf = 0; nf < 8; nf++){
                int col = n0 + wn*64 + nf*8 + 2*(lane & 3);
                float v0 = acc[mf][nf][ri*2 + 0];
                float v1 = acc[mf][nf][ri*2 + 1];
                if (EPI == 1){
                    float s0 = ep[col]   * rsqrtf(ep[3*N+col]   + EPS);
                    float s1 = ep[col+1] * rsqrtf(ep[3*N+col+1] + EPS);
                    v0 = gelu_f(v0 * s0 + ep[N+col]   - ep[2*N+col]   * s0);
                    v1 = gelu_f(v1 * s1 + ep[N+col+1] - ep[2*N+col+1] * s1);
                } else if (EPI == 2){
                    v0 = gelu_f(v0 + ep[col]);
                    v1 = gelu_f(v1 + ep[col+1]);
                } else if (EPI == 3){
                    float2 rr2 = *(const float2*)(res + base + col);
                    v0 = rr2.x + v0 + ep[col];
                    v1 = rr2.y + v1 + ep[col+1];
                } else if (EPI == 4){
                    float2 rr2 = *(const float2*)(res + base + col);
                    v0 = rr2.x + v0;
                    v1 = rr2.y + v1;
                }
                if (OBF){
                    ((unsigned*)Cout)[(base + col) >> 1] = pack_bf(v0, v1);
                } else {
                    *(float2*)((float*)Cout + base + col) = make_float2(v0, v1);
                }
            }
        }
    }
}

// ---------------- geometry prior: 512->1 projection ----------------
__global__ void k_gp_pw(const float* __restrict__ dsf, const float* __restrict__ w,
                        const float* __restrict__ bias, float* __restrict__ ds)
{
    __shared__ float red[8][33];
    int px = threadIdx.x & 31;
    int cz = threadIdx.x >> 5;
    int p0 = blockIdx.x * 32;
    int b  = p0 >> 10;
    int p  = (p0 & (CHW-1)) + px;
    float acc = 0.f;
#pragma unroll
    for (int i = 0; i < 64; i++){
        int c = cz*64 + i;
        acc += w[c] * dsf[((size_t)b*CC + c)*CHW + p];
    }
    red[cz][px] = acc;
    __syncthreads();
    if (cz == 0){
        float s = 0.f;
#pragma unroll
        for (int z = 0; z < 8; z++) s += red[z][px];
        ds[p0 + px] = s + bias[0];
    }
}

// ---------------- prompt: pool + embed + LN -> writes into jt rows 0..7 ----------------
__global__ void k_prompt(const float* __restrict__ pp2t, const float* __restrict__ pe,
                         const float* __restrict__ lnp, float* __restrict__ jt)
{
    int b = blockIdx.x >> 3, pr = blockIdx.x & 7;
    int iy = pr >> 2, ix = pr & 3;
    int t = threadIdx.x;
    float a0 = 0.f, a1 = 0.f;
    for (int py = 0; py < 16; py++)
        for (int px = 0; px < 8; px++){
            int p = (iy*16 + py)*CWW + ix*8 + px;
            const float* base = pp2t + ((size_t)b*CHW + p)*CC;
            a0 += base[t];
            a1 += base[t + 256];
        }
    a0 = a0 * (1.f/128.f) + pe[pr*CC + t];
    a1 = a1 * (1.f/128.f) + pe[pr*CC + t + 256];
    __shared__ float rs[256], rq[256];
    rs[t] = a0 + a1; rq[t] = a0*a0 + a1*a1;
    __syncthreads();
    for (int s = 128; s > 0; s >>= 1){
        if (t < s){ rs[t] += rs[t+s]; rq[t] += rq[t+s]; }
        __syncthreads();
    }
    float mean = rs[0] * (1.f/512.f);
    float var  = rq[0] * (1.f/512.f) - mean*mean;
    float inv  = rsqrtf(var + EPS);
    size_t o = ((size_t)b*CN + pr) * CC;
    jt[o + t]       = (a0 - mean) * inv * lnp[t]       + lnp[CC + t];
    jt[o + t + 256] = (a1 - mean) * inv * lnp[t + 256] + lnp[CC + t + 256];
}

// ---------------- joint depth scalar per token ----------------
__global__ void k_jd(const float* __restrict__ ds, float* __restrict__ jd)
{
    int t = blockIdx.x * 256 + threadIdx.x;
    if (t >= CB*CN) return;
    int b = t / CN, n = t % CN;
    if (n >= NPR){
        jd[t] = ds[b*CHW + (n - NPR)];
    } else {
        int iy = n >> 2, ix = n & 3;
        float acc = 0.f;
        for (int py = 0; py < 16; py++)
            for (int px = 0; px < 8; px++)
                acc += ds[b*CHW + (iy*16 + py)*CWW + ix*8 + px];
        jd[t] = acc * (1.f/128.f);
    }
}

// ---------------- layernorm over C per token (fp32 in, bf16 out) ----------------
__global__ void k_ln(const float* __restrict__ in, const float* __restrict__ p,
                     __nv_bfloat16* __restrict__ out)
{
    int tok = blockIdx.x;
    const float* row = in + (size_t)tok * CC;
    int t = threadIdx.x;
    float v0 = row[t], v1 = row[t + 256];
    __shared__ float rs[256], rq[256];
    rs[t] = v0 + v1; rq[t] = v0*v0 + v1*v1;
    __syncthreads();
    for (int s = 128; s > 0; s >>= 1){
        if (t < s){ rs[t] += rs[t+s]; rq[t] += rq[t+s]; }
        __syncthreads();
    }
    float mean = rs[0] * (1.f/512.f);
    float var  = rq[0] * (1.f/512.f) - mean*mean;
    float inv  = rsqrtf(var + EPS);
    size_t o = (size_t)tok * CC;
    out[o + t]       = __float2bfloat16((v0 - mean) * inv * p[t]       + p[CC + t]);
    out[o + t + 256] = __float2bfloat16((v1 - mean) * inv * p[t + 256] + p[CC + t + 256]);
}

// ---------------- attention: flash, bf16 mma, ldmatrix, cp.async double-buffer ----------------
__device__ __forceinline__ void tok_coord(int n, float& cy, float& cx){
    if (n < NPR){ cy = (float)(n >> 2); cx = (float)(n & 3) * (1.f/3.f); }
    else { int m = n - NPR; cy = (float)(m >> 5) * (1.f/31.f); cx = (float)(m & 31) * (1.f/31.f); }
}

constexpr int AST  = 36;                      // uint row stride (144 B)
constexpr int QS_OFF = 0;                     // 128 rows
constexpr int PS_OFF = 128*AST;               // 128 rows
constexpr int KS_OFF = PS_OFF + 128*AST;      // 2 stages x 64 rows
constexpr int STGK   = 64*AST;                // uints per K/V stage
constexpr int VS_OFF = KS_OFF + 2*STGK;
constexpr int KD_OFF = VS_OFF + 2*STGK;       // 2 x 64 floats
constexpr int ATTN_SMEM = (KD_OFF + 128) * 4;

__global__ void __launch_bounds__(256) k_attn(const __nv_bfloat16* __restrict__ qkv,
                                              const float* __restrict__ jd,
                                              const float* __restrict__ gw,
                                              __nv_bfloat16* __restrict__ ao)
{
    extern __shared__ unsigned smu[];
    unsigned* Qs = smu + QS_OFF;
    unsigned* Ps = smu + PS_OFF;
    float*  kdep = (float*)(smu + KD_OFF);
    unsigned qs_u = su32(Qs), ps_u = su32(Ps);
    unsigned ks_u = su32(smu + KS_OFF), vs_u = su32(smu + VS_OFF);
    unsigned kd_u = su32(kdep);

    int b = blockIdx.z, h = blockIdx.y, q0 = blockIdx.x * 128;
    int tid = threadIdx.x, lane = tid & 31, w = tid >> 5;
    int c = lane & 3, gr = lane >> 2;

    const float decay = logf(1.f - exp2f(-1.f - 0.5f * (float)h));
    const float w0 = gw[0] * decay, w1 = gw[1] * decay;

    // load Q tile (128 x 64 bf16)
#pragma unroll
    for (int j = 0; j < 4; j++){
        int i = tid + 256*j;
        int r = i >> 3, c4 = i & 7;
        int qn = q0 + r;
        uint4 v = (qn < CN) ? *(const uint4*)(qkv + ((size_t)b*CN + qn)*QKV + h*64 + c4*8)
                            : make_uint4(0,0,0,0);
        *(uint4*)&Qs[r*AST + c4*4] = v;
    }

    // K/V/kdep stage loader
    int lr = tid >> 3, lc = tid & 7;   // chunk row/col for first of 2
    auto load_kv = [&](int kt){
        int k0 = kt * 64;
        unsigned st = (unsigned)(kt & 1);
#pragma unroll
        for (int j = 0; j < 2; j++){
            int r = lr + j*32;
            int n = k0 + r;
            bool val = (n < CN);
            const __nv_bfloat16* rowp = qkv + ((size_t)b*CN + n)*QKV + h*64;
            unsigned doff = st*STGK*4 + r*144 + lc*16;
            cp16(ks_u + doff, rowp + CC     + lc*8, val);
            cp16(vs_u + doff, rowp + 2*CC   + lc*8, val);
        }
        if (tid < 16){
            bool val = (k0 + tid*4 + 4) <= CN;
            cp16(kd_u + st*256 + tid*16, jd + (size_t)b*CN + k0 + tid*4, val);
        }
        cp_commit();
    };

    // q-row metadata
    float qy[2], qx[2], qd[2];
#pragma unroll
    for (int i = 0; i < 2; i++){
        int qn = q0 + w*16 + gr + i*8;
        if (qn < CN){ tok_coord(qn, qy[i], qx[i]); qd[i] = jd[b*CN + qn]; }
        else { qy[i] = qx[i] = qd[i] = 0.f; }
    }

    float O[8][4];
#pragma unroll
    for (int nf = 0; nf < 8; nf++)
#pragma unroll
        for (int r = 0; r < 4; r++) O[nf][r] = 0.f;
    float mi[2] = {-1e30f, -1e30f}, li[2] = {0.f, 0.f};

    // fragment bases
    unsigned q_base = qs_u + (w*16 + (lane & 15))*144 + (lane >> 4)*16;
    unsigned p_base = ps_u + (w*16 + (lane & 15))*144 + (lane >> 4)*16;
    unsigned k_base[4];
#pragma unroll
    for (int nf2 = 0; nf2 < 4; nf2++)
        k_base[nf2] = ks_u + (nf2*16 + (lane & 7) + ((lane >> 4) & 1)*8)*144 + ((lane >> 3) & 1)*16;
    unsigned v_row = (lane & 15)*144 + (lane >> 4)*16;

    load_kv(0);

    for (int kt = 0; kt < 17; kt++){
        __syncthreads();                 // previous compute done before overwriting its buffer
        if (kt < 16) load_kv(kt + 1);
        if (kt < 16) cp_wait<1>(); else cp_wait<0>();
        __syncthreads();

        unsigned st = (unsigned)(kt & 1);
        unsigned kso = st*STGK*4, vso = st*STGK*4;
        int k0 = kt * 64;
        const float* kd = kdep + st*64;

        // S = Q K^T
        float S[8][4];
#pragma unroll
        for (int nf = 0; nf < 8; nf++)
#pragma unroll
            for (int r = 0; r < 4; r++) S[nf][r] = 0.f;
#pragma unroll
        for (int kf = 0; kf < 4; kf++){
            unsigned a0, a1, a2, a3;
            ldsm4(a0, a1, a2, a3, q_base + kf*32);
#pragma unroll
            for (int nf2 = 0; nf2 < 4; nf2++){
                unsigned b0, b1, b2, b3;
                ldsm4(b0, b1, b2, b3, k_base[nf2] + kso + kf*32);
                mma_bf16(S[nf2*2  ][0], S[nf2*2  ][1], S[nf2*2  ][2], S[nf2*2  ][3], a0,a1,a2,a3, b0,b1);
                mma_bf16(S[nf2*2+1][0], S[nf2*2+1][1], S[nf2*2+1][2], S[nf2*2+1][3], a0,a1,a2,a3, b2,b3);
            }
        }

        // bias + scale + mask
        bool kval[8][2];
#pragma unroll
        for (int nf = 0; nf < 8; nf++){
#pragma unroll
            for (int j = 0; j < 2; j++){
                int kl = nf*8 + c*2 + j;
                int kn = k0 + kl;
                kval[nf][j] = (kn < CN);
                float ky, kx;
                tok_coord(kn, ky, kx);
                float kdv = kd[kl];
#pragma unroll
                for (int i = 0; i < 2; i++){
                    float pos = fabsf(qy[i]-ky) + fabsf(qx[i]-kx);
                    float vv = S[nf][i*2+j]*0.125f + w0*pos + w1*fabsf(qd[i]-kdv);
                    S[nf][i*2+j] = kval[nf][j] ? vv : -1e30f;
                }
            }
        }

        // online softmax
        float alpha[2];
#pragma unroll
        for (int i = 0; i < 2; i++){
            float tm = -1e30f;
#pragma unroll
            for (int nf = 0; nf < 8; nf++){
                tm = fmaxf(tm, S[nf][i*2]);
                tm = fmaxf(tm, S[nf][i*2+1]);
            }
            tm = fmaxf(tm, __shfl_xor_sync(0xffffffffu, tm, 1));
            tm = fmaxf(tm, __shfl_xor_sync(0xffffffffu, tm, 2));
            float mn = fmaxf(mi[i], tm);
            alpha[i] = __expf(mi[i] - mn);
            float ssum = 0.f;
#pragma unroll
            for (int nf = 0; nf < 8; nf++){
#pragma unroll
                for (int j = 0; j < 2; j++){
                    float p = kval[nf][j] ? __expf(S[nf][i*2+j] - mn) : 0.f;
                    S[nf][i*2+j] = p;
                    ssum += p;
                }
            }
            ssum += __shfl_xor_sync(0xffffffffu, ssum, 1);
            ssum += __shfl_xor_sync(0xffffffffu, ssum, 2);
            li[i] = li[i]*alpha[i] + ssum;
            mi[i] = mn;
        }
#pragma unroll
        for (int nf = 0; nf < 8; nf++){
            O[nf][0] *= alpha[0]; O[nf][1] *= alpha[0];
            O[nf][2] *= alpha[1]; O[nf][3] *= alpha[1];
        }
        // write P (bf16 pairs) into warp-private rows
        int rbase = w*16 + gr;
#pragma unroll
        for (int nf = 0; nf < 8; nf++){
#pragma unroll
            for (int i = 0; i < 2; i++){
                Ps[(rbase + i*8)*AST + nf*4 + c] = pack_bf(S[nf][i*2], S[nf][i*2+1]);
            }
        }
        __syncwarp();

        // O += P V   (V via ldmatrix.trans)
#pragma unroll
        for (int kf = 0; kf < 4; kf++){
            unsigned a0, a1, a2, a3;
            ldsm4(a0, a1, a2, a3, p_base + kf*32);
#pragma unroll
            for (int dg = 0; dg < 4; dg++){
                unsigned b0, b1, b2, b3;
                ldsm4t(b0, b1, b2, b3, vs_u + vso + kf*16*144 + v_row + dg*32);
                mma_bf16(O[dg*2  ][0], O[dg*2  ][1], O[dg*2  ][2], O[dg*2  ][3], a0,a1,a2,a3, b0,b1);
                mma_bf16(O[dg*2+1][0], O[dg*2+1][1], O[dg*2+1][2], O[dg*2+1][3], a0,a1,a2,a3, b2,b3);
            }
        }
    }

    // epilogue (bf16)
#pragma unroll
    for (int i = 0; i < 2; i++){
        int qn = q0 + w*16 + gr + i*8;
        if (qn >= CN) continue;
        float invl = 1.f / li[i];
        size_t base = ((size_t)b*CN + qn)*CC + h*64;
#pragma unroll
        for (int nf = 0; nf < 8; nf++){
            int cc2 = nf*8 + c*2;
            ((unsigned*)ao)[(base + cc2) >> 1] = pack_bf(O[nf][i*2]*invl, O[nf][i*2+1]*invl);
        }
    }
}

// ---------------- final: out = fused + BN(op_pw output), with transpose ----------------
__global__ void k_final(const float* __restrict__ fused, const float* __restrict__ o2t,
                        const float* __restrict__ bn, float* __restrict__ out)
{
    __shared__ float tile[32][33];
    int b = blockIdx.z;
    int p0 = blockIdx.x * 32, c0 = blockIdx.y * 32;
    int tx = threadIdx.x, ty = threadIdx.y;
#pragma unroll
    for (int i = 0; i < 4; i++){
        int p = p0 + ty + i*8;
        tile[ty + i*8][tx] = o2t[((size_t)b*CHW + p)*CC + c0 + tx];
    }
    __syncthreads();
#pragma unroll
    for (int i = 0; i < 4; i++){
        int c = c0 + ty + i*8;
        float s = bn[c] * rsqrtf(bn[3*CC+c] + EPS);
        float t = bn[CC+c] - bn[2*CC+c] * s;
        size_t idx = ((size_t)b*CC + c)*CHW + p0 + tx;
        out[idx] = fused[idx] + tile[tx][ty + i*8] * s + t;
    }
}

// ---------------- host ----------------
template<int EPI, int OBF>
static void gemm_go(const __nv_bfloat16* A, const __nv_bfloat16* Bw, void* Cm,
                    int M, int N, int K, const float* ep, const float* res)
{
    cudaFuncSetAttribute(k_gemm_bf<EPI,OBF>, cudaFuncAttributeMaxDynamicSharedMemorySize, GEMM_SMEM);
    dim3 g(N/128, (M + 127)/128);
    k_gemm_bf<EPI,OBF><<<g, 256, GEMM_SMEM>>>(A, Bw, Cm, M, N, K, ep, res);
}

extern "C" void kernel_launch(void* const* d_in, const int* in_sizes, int n_in,
                              void* d_out, int out_size)
{
    const float* fused        = (const float*)d_in[0];
    const float* depth        = (const float*)d_in[1];
    const float* pg_dw_w      = (const float*)d_in[2];
    const float* pg_bn1       = (const float*)d_in[3];
    const float* pg_pw_w      = (const float*)d_in[4];
    const float* pg_bn2       = (const float*)d_in[5];
    const float* prompt_embed = (const float*)d_in[6];
    const float* pg_ln        = (const float*)d_in[7];
    const float* gp_dw_w      = (const float*)d_in[8];
    const float* gp_bn        = (const float*)d_in[9];
    const float* gp_pw_w      = (const float*)d_in[10];
    const float* gp_pw_b      = (const float*)d_in[11];
    const float* gp_weight    = (const float*)d_in[12];
    const float* ln1          = (const float*)d_in[13];
    const float* wq           = (const float*)d_in[14];
    const float* wk           = (const float*)d_in[15];
    const float* wv           = (const float*)d_in[16];
    const float* wo           = (const float*)d_in[17];
    const float* ln2          = (const float*)d_in[18];
    const float* mlp_w1       = (const float*)d_in[19];
    const float* mlp_b1       = (const float*)d_in[20];
    const float* mlp_w2       = (const float*)d_in[21];
    const float* mlp_b2       = (const float*)d_in[22];
    const float* op_dw_w      = (const float*)d_in[23];
    const float* op_bn1       = (const float*)d_in[24];
    const float* op_pw_w      = (const float*)d_in[25];
    const float* op_bn2       = (const float*)d_in[26];

    float *dsf,*pp2t,*ds,*jdb,*jt,*enh,*o2t;
    __nv_bfloat16 *pp1t,*xb,*qkv,*aob,*hb,*o1t,*wall;
    cudaGetSymbolAddress((void**)&dsf,  g_dsf);
    cudaGetSymbolAddress((void**)&pp2t, g_pp2t);
    cudaGetSymbolAddress((void**)&ds,   g_ds);
    cudaGetSymbolAddress((void**)&jdb,  g_jd);
    cudaGetSymbolAddress((void**)&jt,   g_jt);
    cudaGetSymbolAddress((void**)&enh,  g_enh);
    cudaGetSymbolAddress((void**)&o2t,  g_o2t);
    cudaGetSymbolAddress((void**)&pp1t, g_pp1t_bf);
    cudaGetSymbolAddress((void**)&xb,   g_x_bf);
    cudaGetSymbolAddress((void**)&qkv,  g_qkv_bf);
    cudaGetSymbolAddress((void**)&aob,  g_ao_bf);
    cudaGetSymbolAddress((void**)&hb,   g_h_bf);
    cudaGetSymbolAddress((void**)&o1t,  g_o1t_bf);
    cudaGetSymbolAddress((void**)&wall, g_wall);

    cudaFuncSetAttribute(k_attn, cudaFuncAttributeMaxDynamicSharedMemorySize, ATTN_SMEM);

    dim3 tgrid(CHW/32, CC/32, CB), tblk(32, 8);

    // single fused weight pack
    k_pack_all<<<(WALL/4 + 255)/256, 256>>>(pg_pw_w, wq, wk, wv, wo, mlp_w1, mlp_w2, op_pw_w, wall);

    // --- depth branches: fused dwconv + BN + GELU + transpose ---
    k_dwconv_t<1><<<tgrid, tblk>>>(depth, pg_dw_w, pg_bn1, pp1t, gp_dw_w, gp_bn, dsf);
    gemm_go<1,0>(pp1t, wall + OPG, pp2t, CB*CHW, CC, CC, pg_bn2, nullptr);
    k_gp_pw<<<(CB*CHW)/32, 256>>>(dsf, gp_pw_w, gp_pw_b, ds);
    k_prompt<<<CB*NPR, 256>>>(pp2t, prompt_embed, pg_ln, jt);   // writes jt rows 0..7
    k_jd<<<(CB*CN + 255)/256, 256>>>(ds, jdb);

    // image tokens into jt rows 8..
    k_cp_to_tok_f<<<tgrid, tblk>>>(fused, jt, CN, NPR);

    // --- attention block ---
    k_ln<<<CB*CN, 256>>>(jt, ln1, xb);
    gemm_go<0,1>(xb, wall + OQKV, qkv, CB*CN, QKV, CC, nullptr, nullptr);
    k_attn<<<dim3(9, CNH, CB), 256, ATTN_SMEM>>>(qkv, jdb, gp_weight, aob);
    gemm_go<4,0>(aob, wall + OWO, jt, CB*CN, CC, CC, nullptr, jt);

    // --- MLP ---
    k_ln<<<CB*CN, 256>>>(jt, ln2, xb);
    gemm_go<2,1>(xb, wall + OW1, hb, CB*CN, HID, CC, mlp_b1, nullptr);
    gemm_go<3,0>(hb, wall + OW2, jt, CB*CN, CC, HID, mlp_b2, jt);

    // --- out_proj ---
    k_tok_to_cp<<<tgrid, tblk>>>(jt, enh, CN, NPR);
    k_dwconv_t<0><<<tgrid, tblk>>>(enh, op_dw_w, op_bn1, o1t, nullptr, nullptr, nullptr);
    gemm_go<0,0>(o1t, wall + OWOP, o2t, CB*CHW, CC, CC, nullptr, nullptr);
    k_final<<<tgrid, tblk>>>(fused, o2t, op_bn2, (float*)d_out);
}